// round 11
// baseline (speedup 1.0000x reference)
#include <cuda_runtime.h>
#include <math.h>

#define NBATCH 64
#define NSTEP  128
#define MEMD   128
#define NSLOT  20
#define HSLOT  10
#define NCTA   128
#define OUTC   160
#define RSTR   12      // floats per mem_s row (48B, 16B aligned)

__device__ float g_S [NBATCH * NSTEP * MEMD];
__device__ float g_O [NBATCH * NSTEP * OUTC];
__device__ float g_WK[OUTC * MEMD];
__device__ float g_BK[OUTC];
__device__ float g_VK[NSLOT * MEMD];
__device__ uint2 g_part[NSTEP][NSLOT][NBATCH];   // {value bits, tag = t+1}
__device__ uint2 g_inv [NSTEP][NSLOT];           // {inv bits, tag = t+1} (leader-reduced)
__device__ float g_H [NBATCH * NSLOT * MEMD];

// ---------- helpers ----------
__device__ __forceinline__ void ffma2(unsigned long long &acc, unsigned long long a,
                                      unsigned long long b) {
    asm("fma.rn.f32x2 %0, %1, %2, %0;" : "+l"(acc) : "l"(a), "l"(b));
}
__device__ __forceinline__ unsigned long long add2(unsigned long long a,
                                                   unsigned long long b) {
    unsigned long long r;
    asm("add.rn.f32x2 %0, %1, %2;" : "=l"(r) : "l"(a), "l"(b));
    return r;
}
__device__ __forceinline__ unsigned long long pack2(float x) {
    unsigned long long r; asm("mov.b64 %0, {%1, %1};" : "=l"(r) : "f"(x)); return r;
}
__device__ __forceinline__ float2 up2(unsigned long long v) {
    float2 r; asm("mov.b64 {%0, %1}, %2;" : "=f"(r.x), "=f"(r.y) : "l"(v)); return r;
}
__device__ __forceinline__ unsigned smem_u32(const void* p) {
    return (unsigned)__cvta_generic_to_shared(p);
}
__device__ __forceinline__ void ld_row10(unsigned addr,
    unsigned long long &m0, unsigned long long &m1, unsigned long long &m2,
    unsigned long long &m3, unsigned long long &m4) {
    asm("{\n\t"
        ".reg .b32 t0,t1,t2,t3,t4,t5,t6,t7,t8,t9;\n\t"
        "ld.shared.v4.b32 {t0,t1,t2,t3}, [%5];\n\t"
        "ld.shared.v4.b32 {t4,t5,t6,t7}, [%5+16];\n\t"
        "ld.shared.v2.b32 {t8,t9}, [%5+32];\n\t"
        "mov.b64 %0, {t0,t1};\n\t"
        "mov.b64 %1, {t2,t3};\n\t"
        "mov.b64 %2, {t4,t5};\n\t"
        "mov.b64 %3, {t6,t7};\n\t"
        "mov.b64 %4, {t8,t9};\n\t"
        "}"
        : "=l"(m0), "=l"(m1), "=l"(m2), "=l"(m3), "=l"(m4) : "r"(addr));
}
__device__ __forceinline__ uint2 ldv2(const uint2* p) {
    uint2 v;
    asm volatile("ld.volatile.global.v2.u32 {%0,%1}, [%2];"
                 : "=r"(v.x), "=r"(v.y) : "l"(p) : "memory");
    return v;
}
__device__ __forceinline__ void stv2(uint2* p, uint2 v) {
    asm volatile("st.volatile.global.v2.u32 [%0], {%1,%2};"
                 :: "l"(p), "r"(v.x), "r"(v.y) : "memory");
}
__device__ __forceinline__ float sig(float x) { return 1.f / (1.f + __expf(-x)); }

// ---------- prologue: weights pack + Vkey + zero tag buffers ----------
__global__ void k_setup(const float* __restrict__ Ww, const float* __restrict__ Wb,
                        const float* __restrict__ sk, const float* __restrict__ Vw,
                        const float* __restrict__ Vb) {
    int bid = blockIdx.x, tid = threadIdx.x;
    if (bid < NSLOT) {
        float acc = Vb[tid];
        const float* skr = sk + bid * MEMD;
        const float* vwr = Vw + tid * MEMD;
        #pragma unroll 8
        for (int m = 0; m < MEMD; m++) acc += skr[m] * vwr[m];
        g_VK[bid * MEMD + tid] = acc;
    } else if (bid == NSLOT) {
        for (int idx = tid; idx < OUTC * MEMD; idx += 128) {
            int c = idx >> 7, m = idx & 127;
            float v = 0.f;
            if (c < 128)      v = Ww[c * MEMD + m];
            else if (c < 148) v = sk[(c - 128) * MEMD + m];
            g_WK[idx] = v;
        }
        for (int idx = tid; idx < OUTC; idx += 128)
            g_BK[idx] = (idx < 128) ? Wb[idx] : 0.f;
    } else if (bid == NSLOT + 1) {
        // zero g_inv: 1280 uint4
        for (int i = tid; i < 1280; i += 128)
            ((uint4*)g_inv)[i] = make_uint4(0u, 0u, 0u, 0u);
    } else {
        // zero g_part: 81920 uint4, blocks 22..341, 128 thr x 2 each
        int base = (bid - 22) * 128 + tid;
        ((uint4*)g_part)[base]         = make_uint4(0u, 0u, 0u, 0u);
        ((uint4*)g_part)[base + 40960] = make_uint4(0u, 0u, 0u, 0u);
    }
}

// ---------- fused gather + GEMM (512 thr): OUT[row][c] = E[tok[row]].WK[c] + BK[c] ----------
__global__ void __launch_bounds__(512) k_gemm(const int* __restrict__ ids,
                                              const float* __restrict__ E) {
    __shared__ int   toks[64];
    __shared__ float Ss[64][33];
    __shared__ float Ks[OUTC][33];
    int tid = threadIdx.x, row0 = blockIdx.x * 64;
    int tx = tid & 15, ty = tid >> 4;            // tx: 10 cols, ty: 2 rows
    if (tid < 64) {
        int row = row0 + tid;
        toks[tid] = ids[(row >> 7) * 4096 + (row & 127)];
    }
    __syncthreads();
    float acc[2][10];
    #pragma unroll
    for (int i = 0; i < 2; i++)
        #pragma unroll
        for (int j = 0; j < 10; j++) acc[i][j] = 0.f;
    for (int kk = 0; kk < 128; kk += 32) {
        #pragma unroll
        for (int i = 0; i < 4; i++) {
            int idx = tid + i * 512, r = idx >> 5, k = idx & 31;
            float v = E[toks[r] * 128 + kk + k];
            Ss[r][k] = v;
            g_S[(row0 + r) * 128 + kk + k] = v;
        }
        #pragma unroll
        for (int i = 0; i < 10; i++) {
            int idx = tid + i * 512, c = idx >> 5, k = idx & 31;
            Ks[c][k] = g_WK[c * 128 + kk + k];
        }
        __syncthreads();
        #pragma unroll
        for (int k = 0; k < 32; k++) {
            float a[2], bv[10];
            #pragma unroll
            for (int i = 0; i < 2; i++)  a[i]  = Ss[ty * 2 + i][k];
            #pragma unroll
            for (int j = 0; j < 10; j++) bv[j] = Ks[tx * 10 + j][k];
            #pragma unroll
            for (int i = 0; i < 2; i++)
                #pragma unroll
                for (int j = 0; j < 10; j++) acc[i][j] = fmaf(a[i], bv[j], acc[i][j]);
        }
        __syncthreads();
    }
    #pragma unroll
    for (int i = 0; i < 2; i++)
        #pragma unroll
        for (int j = 0; j < 10; j++) {
            int r = row0 + ty * 2 + i, c = tx * 10 + j;
            g_O[r * OUTC + c] = acc[i][j] + g_BK[c];
        }
}

// ---------- persistent scan: R5/R10 structure + two-level inv broadcast ----------
__global__ void __launch_bounds__(512, 1) k_main(const float* __restrict__ Uw,
                                                 const float* __restrict__ Ub) {
    __shared__ float mem_s[128 * RSTR];          // RAW (unnormalized) mem
    __shared__ float vk_s[HSLOT][128];
    __shared__ float s_b[2][128], ws_b[2][128];  // double-buffered staging
    __shared__ float sk_b[2][12];
    __shared__ float red_s[8][5];                // gate partials
    __shared__ float red2_s[16][4];              // sumsq partials per warp
    __shared__ float inv_s[HSLOT];
    __shared__ unsigned long long comb[5][4][128];  // [pair][quarter][n]

    const int tid = threadIdx.x;
    const int n = tid & 127, q = tid >> 7, wid = tid >> 5, lane = tid & 31;
    const int cta = blockIdx.x, b = cta >> 1, half = cta & 1;
    const bool leader = (b == 0);                // cta 0 / cta 1

    // pre-packed Uw column slice: 32 rows of this thread's k-quarter
    unsigned long long uwr2[32];
    {
        const float4* up = (const float4*)(Uw + n * 128 + q * 32);
        #pragma unroll
        for (int i = 0; i < 8; i++) {
            float4 v = up[i];
            uwr2[4*i]   = pack2(v.x); uwr2[4*i+1] = pack2(v.y);
            uwr2[4*i+2] = pack2(v.z); uwr2[4*i+3] = pack2(v.w);
        }
    }
    const float ubn = Ub[n];
    for (int idx = tid; idx < HSLOT * 128; idx += 512)
        vk_s[idx >> 7][idx & 127] = g_VK[(half * HSLOT + (idx >> 7)) * 128 + (idx & 127)];
    for (int idx = tid; idx < 128 * RSTR; idx += 512) mem_s[idx] = 0.f;

    float memv[4];
    #pragma unroll
    for (int i = 0; i < 4; i++) memv[i] = 0.f;

    const float* Sb = g_S + b * 128 * 128;
    const float* Ob = g_O + b * 128 * OUTC;
    if (q == 0) { s_b[0][n] = Sb[n]; ws_b[0][n] = Ob[n]; }
    else if (q == 1 && n < HSLOT) sk_b[0][n] = Ob[128 + half * HSLOT + n];
    if (tid < HSLOT) inv_s[tid] = 1.f;           // t=0: mem is exactly zero
    __syncthreads();

    const unsigned mem_u32 = smem_u32(mem_s) + q * 32 * (RSTR * 4);

    for (int t = 0; t < NSTEP; t++) {
        const int cur = t & 1, nxt = cur ^ 1;

        // ---- A. q0/q1: staging prefetch; q2/q3: raw gate dots ----
        float s_nxt = 0.f, ws_nxt = 0.f, skey_nxt = 0.f;
        if (q < 2) {
            int tn = (t + 1) & 127;
            if (q == 0) { s_nxt = Sb[tn * 128 + n]; ws_nxt = Ob[tn * OUTC + n]; }
            else if (n < HSLOT) skey_nxt = Ob[tn * OUTC + 128 + half * HSLOT + n];
        } else {
            float sv = s_b[cur][n];
            const float* row = mem_s + n * RSTR + (q - 2) * 5;
            float p0 = sv * row[0], p1 = sv * row[1], p2 = sv * row[2];
            float p3 = sv * row[3], p4 = sv * row[4];
            #pragma unroll
            for (int s = 16; s; s >>= 1) {
                p0 += __shfl_xor_sync(~0u, p0, s);
                p1 += __shfl_xor_sync(~0u, p1, s);
                p2 += __shfl_xor_sync(~0u, p2, s);
                p3 += __shfl_xor_sync(~0u, p3, s);
                p4 += __shfl_xor_sync(~0u, p4, s);
            }
            if (lane == 0) {
                float* rr = red_s[wid - 8];
                rr[0] = p0; rr[1] = p1; rr[2] = p2; rr[3] = p3; rr[4] = p4;
            }
        }

        // ---- B. matmul quarter: 32 rows x (3 LDS + 5 FFMA2) ----
        unsigned long long accv[5];
        #pragma unroll
        for (int p = 0; p < 5; p++) accv[p] = 0ull;
        #pragma unroll
        for (int k = 0; k < 32; k++) {
            unsigned long long m0, m1, m2, m3, m4;
            ld_row10(mem_u32 + k * (RSTR * 4), m0, m1, m2, m3, m4);
            ffma2(accv[0], uwr2[k], m0);
            ffma2(accv[1], uwr2[k], m1);
            ffma2(accv[2], uwr2[k], m2);
            ffma2(accv[3], uwr2[k], m3);
            ffma2(accv[4], uwr2[k], m4);
        }
        #pragma unroll
        for (int p = 0; p < 5; p++) comb[p][q][n] = accv[p];

        // ---- C. norm exchange ----
        if (t) {
            if (leader) {
                // leader: full gather (warps 0-4), publish reduced inv
                if (wid < 5) {
                    int j = tid >> 4, i = tid & 15;
                    const uint2* pp = &g_part[t - 1][half * HSLOT + j][i];
                    const unsigned want = (unsigned)t;
                    uint2 v0 = ldv2(pp), v1 = ldv2(pp + 16), v2 = ldv2(pp + 32), v3 = ldv2(pp + 48);
                    while ((v0.y ^ want) | (v1.y ^ want) | (v2.y ^ want) | (v3.y ^ want)) {
                        v0 = ldv2(pp); v1 = ldv2(pp + 16); v2 = ldv2(pp + 32); v3 = ldv2(pp + 48);
                    }
                    float acc = __uint_as_float(v0.x) + __uint_as_float(v1.x)
                              + __uint_as_float(v2.x) + __uint_as_float(v3.x);
                    acc += __shfl_xor_sync(~0u, acc, 8);
                    acc += __shfl_xor_sync(~0u, acc, 4);
                    acc += __shfl_xor_sync(~0u, acc, 2);
                    acc += __shfl_xor_sync(~0u, acc, 1);
                    if (i == 0) {
                        float iv = rsqrtf(acc);
                        inv_s[j] = iv;
                        uint2 pk; pk.x = __float_as_uint(iv); pk.y = (unsigned)t;
                        stv2(&g_inv[t - 1][half * HSLOT + j], pk);
                    }
                }
            } else if (wid == 0 && lane < HSLOT) {
                // follower: poll 10 reduced inv values (per-thread independent exit)
                const uint2* pp = &g_inv[t - 1][half * HSLOT + lane];
                const unsigned want = (unsigned)t;
                uint2 v;
                do { v = ldv2(pp); } while (v.y != want);
                inv_s[lane] = __uint_as_float(v.x);
            }
        }
        __syncthreads();   // comb + red_s + inv_s all visible

        // ---- D. epilogue: combine quarters, gate, relu, update, sumsq ----
        const float wsv = ws_b[cur][n];
        float* row = mem_s + n * RSTR;
        if (q == 0) {
            float sq[4];
            #pragma unroll
            for (int p = 0; p < 2; p++) {
                unsigned long long tot = add2(add2(comb[p][0][n], comb[p][1][n]),
                                              add2(comb[p][2][n], comb[p][3][n]));
                float2 a = up2(tot);
                const int j0 = 2 * p, j1 = 2 * p + 1;
                float r0 = red_s[0][j0] + red_s[1][j0] + red_s[2][j0] + red_s[3][j0];
                float r1 = red_s[0][j1] + red_s[1][j1] + red_s[2][j1] + red_s[3][j1];
                float i0 = inv_s[j0], i1 = inv_s[j1];
                float g0 = sig(fmaf(i0, r0, sk_b[cur][j0]));
                float g1 = sig(fmaf(i1, r1, sk_b[cur][j1]));
                float h0 = fmaxf(fmaf(i0, a.x, ubn + vk_s[j0][n] + wsv), 0.f);
                float h1 = fmaxf(fmaf(i1, a.y, ubn + vk_s[j1][n] + wsv), 0.f);
                memv[j0] = fmaf(memv[j0], i0, g0 * h0);
                memv[j1] = fmaf(memv[j1], i1, g1 * h1);
                sq[j0] = memv[j0] * memv[j0];
                sq[j1] = memv[j1] * memv[j1];
            }
            #pragma unroll
            for (int s = 16; s; s >>= 1)
                #pragma unroll
                for (int i = 0; i < 4; i++) sq[i] += __shfl_xor_sync(~0u, sq[i], s);
            if (lane == 0) {
                red2_s[wid][0] = sq[0]; red2_s[wid][1] = sq[1];
                red2_s[wid][2] = sq[2]; red2_s[wid][3] = sq[3];
            }
            *(float4*)row = make_float4(memv[0], memv[1], memv[2], memv[3]);
            s_b[nxt][n] = s_nxt; ws_b[nxt][n] = ws_nxt;
        } else {
            const int p = q + 1;                 // pair owned: q1->2, q2->3, q3->4
            const int j0 = 2 * p, j1 = 2 * p + 1;
            unsigned long long tot = add2(add2(comb[p][0][n], comb[p][1][n]),
                                          add2(comb[p][2][n], comb[p][3][n]));
            float2 a = up2(tot);
            float r0 = (j0 < 5) ? red_s[0][j0] + red_s[1][j0] + red_s[2][j0] + red_s[3][j0]
                                : red_s[4][j0-5] + red_s[5][j0-5] + red_s[6][j0-5] + red_s[7][j0-5];
            float r1 = (j1 < 5) ? red_s[0][j1] + red_s[1][j1] + red_s[2][j1] + red_s[3][j1]
                                : red_s[4][j1-5] + red_s[5][j1-5] + red_s[6][j1-5] + red_s[7][j1-5];
            float i0 = inv_s[j0], i1 = inv_s[j1];
            float g0 = sig(fmaf(i0, r0, sk_b[cur][j0]));
            float g1 = sig(fmaf(i1, r1, sk_b[cur][j1]));
            float h0 = fmaxf(fmaf(i0, a.x, ubn + vk_s[j0][n] + wsv), 0.f);
            float h1 = fmaxf(fmaf(i1, a.y, ubn + vk_s[j1][n] + wsv), 0.f);
            memv[0] = fmaf(memv[0], i0, g0 * h0);
            memv[1] = fmaf(memv[1], i1, g1 * h1);
            float sq0 = memv[0] * memv[0], sq1 = memv[1] * memv[1];
            #pragma unroll
            for (int s = 16; s; s >>= 1) {
                sq0 += __shfl_xor_sync(~0u, sq0, s);
                sq1 += __shfl_xor_sync(~0u, sq1, s);
            }
            if (lane == 0) { red2_s[wid][0] = sq0; red2_s[wid][1] = sq1; }
            *(float2*)(row + j0) = make_float2(memv[0], memv[1]);
            if (q == 1 && n < HSLOT) sk_b[nxt][n] = skey_nxt;
        }
        __syncthreads();   // mem(t+1) + red2_s + staging visible

        // ---- E. publish tagged sumsq partials ----
        if (tid < HSLOT) {
            int j = tid;
            int qo  = (j < 4) ? 0 : (j < 6) ? 1 : (j < 8) ? 2 : 3;
            int idx = (j < 4) ? j : (j - 4) & 1;
            int w0 = qo * 4;
            float v = red2_s[w0][idx] + red2_s[w0+1][idx] + red2_s[w0+2][idx] + red2_s[w0+3][idx];
            uint2 pkt; pkt.x = __float_as_uint(v); pkt.y = (unsigned)(t + 1);
            stv2(&g_part[t][half * HSLOT + j][b], pkt);
        }
    }

    // ---- final normalization ----
    if (leader) {
        if (wid < 5) {
            int j = tid >> 4, i = tid & 15;
            const uint2* pp = &g_part[NSTEP - 1][half * HSLOT + j][i];
            const unsigned want = (unsigned)NSTEP;
            uint2 v0 = ldv2(pp), v1 = ldv2(pp + 16), v2 = ldv2(pp + 32), v3 = ldv2(pp + 48);
            while ((v0.y ^ want) | (v1.y ^ want) | (v2.y ^ want) | (v3.y ^ want)) {
                v0 = ldv2(pp); v1 = ldv2(pp + 16); v2 = ldv2(pp + 32); v3 = ldv2(pp + 48);
            }
            float acc = __uint_as_float(v0.x) + __uint_as_float(v1.x)
                      + __uint_as_float(v2.x) + __uint_as_float(v3.x);
            acc += __shfl_xor_sync(~0u, acc, 8);
            acc += __shfl_xor_sync(~0u, acc, 4);
            acc += __shfl_xor_sync(~0u, acc, 2);
            acc += __shfl_xor_sync(~0u, acc, 1);
            if (i == 0) {
                float iv = rsqrtf(acc);
                inv_s[j] = iv;
                uint2 pk; pk.x = __float_as_uint(iv); pk.y = (unsigned)NSTEP;
                stv2(&g_inv[NSTEP - 1][half * HSLOT + j], pk);
            }
        }
    } else if (wid == 0 && lane < HSLOT) {
        const uint2* pp = &g_inv[NSTEP - 1][half * HSLOT + lane];
        const unsigned want = (unsigned)NSTEP;
        uint2 v;
        do { v = ldv2(pp); } while (v.y != want);
        inv_s[lane] = __uint_as_float(v.x);
    }
    __syncthreads();

    {
        float* gh = g_H + b * (NSLOT * MEMD) + half * HSLOT * MEMD;
        if (q == 0) {
            #pragma unroll
            for (int j = 0; j < 4; j++) gh[j * MEMD + n] = memv[j] * inv_s[j];
        } else {
            const int j0 = 2 * (q + 1);
            gh[j0 * MEMD + n]       = memv[0] * inv_s[j0];
            gh[(j0 + 1) * MEMD + n] = memv[1] * inv_s[j0 + 1];
        }
    }
}

// ---------- epilogue ----------
__global__ void k_epi(const int* __restrict__ q, const int* __restrict__ ans,
                      const float* __restrict__ E, const float* __restrict__ Hw,
                      const float* __restrict__ Hb, float* __restrict__ out) {
    __shared__ float red[4][NSLOT];
    __shared__ float p_s[NSLOT];
    __shared__ __align__(16) float u_s[MEMD];
    __shared__ float yr[4][2];
    int b = blockIdx.x, n = threadIdx.x, w = n >> 5, l = n & 31;

    float qv = 0.f;
    #pragma unroll
    for (int i = 0; i < 16; i++) qv += E[q[b * 16 + i] * MEMD + n];
    qv *= (1.f / 16.f);
    float a1 = 0.f, a2 = 0.f;
    #pragma unroll
    for (int i = 0; i < 8; i++) {
        a1 += E[ans[(b * 8 + i) * 2 + 0] * MEMD + n];
        a2 += E[ans[(b * 8 + i) * 2 + 1] * MEMD + n];
    }
    a1 *= 0.125f; a2 *= 0.125f;

    float hv[NSLOT], p[NSLOT];
    #pragma unroll
    for (int jj = 0; jj < NSLOT; jj++) {
        hv[jj] = g_H[b * (NSLOT * MEMD) + jj * MEMD + n];
        p[jj] = hv[jj] * qv;
    }
    #pragma unroll
    for (int s = 16; s; s >>= 1)
        #pragma unroll
        for (int jj = 0; jj < NSLOT; jj++) p[jj] += __shfl_xor_sync(~0u, p[jj], s);
    if (l == 0) {
        #pragma unroll
        for (int jj = 0; jj < NSLOT; jj++) red[w][jj] = p[jj];
    }
    __syncthreads();
    if (n == 0) {
        float d[NSLOT], mx = -1e30f;
        #pragma unroll
        for (int jj = 0; jj < NSLOT; jj++) {
            d[jj] = red[0][jj] + red[1][jj] + red[2][jj] + red[3][jj];
            mx = fmaxf(mx, d[jj]);
        }
        float sm = 0.f;
        #pragma unroll
        for (int jj = 0; jj < NSLOT; jj++) { d[jj] = expf(d[jj] - mx); sm += d[jj]; }
        float inv = 1.f / sm;
        #pragma unroll
        for (int jj = 0; jj < NSLOT; jj++) p_s[jj] = d[jj] * inv;
    }
    __syncthreads();

    float u = 0.f;
    #pragma unroll
    for (int jj = 0; jj < NSLOT; jj++) u = fmaf(p_s[jj], hv[jj], u);
    u_s[n] = u;
    __syncthreads();

    // Hw matvec: 4 independent FMA chains, float4 loads
    float r0 = 0.f, r1 = 0.f, r2 = 0.f, r3 = 0.f;
    const float4* hw4 = (const float4*)(Hw + n * MEMD);
    const float4* u4  = (const float4*)u_s;
    #pragma unroll
    for (int i = 0; i < 32; i += 4) {
        float4 h0 = hw4[i],     x0 = u4[i];
        float4 h1 = hw4[i + 1], x1 = u4[i + 1];
        float4 h2 = hw4[i + 2], x2 = u4[i + 2];
        float4 h3 = hw4[i + 3], x3 = u4[i + 3];
        r0 = fmaf(x0.x, h0.x, fmaf(x0.y, h0.y, fmaf(x0.z, h0.z, fmaf(x0.w, h0.w, r0))));
        r1 = fmaf(x1.x, h1.x, fmaf(x1.y, h1.y, fmaf(x1.z, h1.z, fmaf(x1.w, h1.w, r1))));
        r2 = fmaf(x2.x, h2.x, fmaf(x2.y, h2.y, fmaf(x2.z, h2.z, fmaf(x2.w, h2.w, r2))));
        r3 = fmaf(x3.x, h3.x, fmaf(x3.y, h3.y, fmaf(x3.z, h3.z, fmaf(x3.w, h3.w, r3))));
    }
    float r = fmaxf(qv + Hb[n] + ((r0 + r1) + (r2 + r3)), 0.f);

    float y1 = r * a1, y2 = r * a2;
    #pragma unroll
    for (int s = 16; s; s >>= 1) {
        y1 += __shfl_xor_sync(~0u, y1, s);
        y2 += __shfl_xor_sync(~0u, y2, s);
    }
    if (l == 0) { yr[w][0] = y1; yr[w][1] = y2; }
    __syncthreads();
    if (n == 0) {
        float s1 = yr[0][0] + yr[1][0] + yr[2][0] + yr[3][0];
        float s2 = yr[0][1] + yr[1][1] + yr[2][1] + yr[3][1];
        float mx = fmaxf(s1, s2);
        float e1 = expf(s1 - mx), e2 = expf(s2 - mx);
        float inv = 1.f / (e1 + e2);
        out[b * 2 + 0] = e1 * inv;
        out[b * 2 + 1] = e2 * inv;
    }
}

extern "C" void kernel_launch(void* const* d_in, const int* in_sizes, int n_in,
                              void* d_out, int out_size) {
    const int*   input_ids = (const int*)  d_in[0];
    const int*   question  = (const int*)  d_in[1];
    const int*   ans       = (const int*)  d_in[2];
    const float* E         = (const float*)d_in[3];
    const float* Uw        = (const float*)d_in[4];
    const float* Ub        = (const float*)d_in[5];
    const float* Vw        = (const float*)d_in[6];
    const float* Vb        = (const float*)d_in[7];
    const float* Ww        = (const float*)d_in[8];
    const float* Wb        = (const float*)d_in[9];
    const float* sk        = (const float*)d_in[10];
    const float* Hw        = (const float*)d_in[11];
    const float* Hb        = (const float*)d_in[12];
    float* out = (float*)d_out;

    k_setup <<<342, 128>>>(Ww, Wb, sk, Vw, Vb);
    k_gemm  <<<128, 512>>>(input_ids, E);
    k_main  <<<NCTA, 512>>>(Uw, Ub);
    k_epi   <<<64, 128>>>(question, ans, E, Hw, Hb, out);
}

// round 12
// speedup vs baseline: 1.0829x; 1.0829x over previous
#include <cuda_runtime.h>
#include <math.h>

#define NBATCH 64
#define NSTEP  128
#define MEMD   128
#define NSLOT  20
#define HSLOT  10
#define NCTA   128
#define OUTC   160
#define RSTR   12      // floats per mem_s row (48B, 16B aligned)

__device__ float g_S [NBATCH * NSTEP * MEMD];
__device__ float g_O [NBATCH * NSTEP * OUTC];
__device__ float g_VK[NSLOT * MEMD];
__device__ uint2 g_part[NSTEP][NSLOT][NBATCH];   // {value bits, tag = t+1}
__device__ float g_H [NBATCH * NSLOT * MEMD];

// ---------- helpers ----------
__device__ __forceinline__ void ffma2(unsigned long long &acc, unsigned long long a,
                                      unsigned long long b) {
    asm("fma.rn.f32x2 %0, %1, %2, %0;" : "+l"(acc) : "l"(a), "l"(b));
}
__device__ __forceinline__ unsigned long long add2(unsigned long long a,
                                                   unsigned long long b) {
    unsigned long long r;
    asm("add.rn.f32x2 %0, %1, %2;" : "=l"(r) : "l"(a), "l"(b));
    return r;
}
__device__ __forceinline__ unsigned long long pack2(float x) {
    unsigned long long r; asm("mov.b64 %0, {%1, %1};" : "=l"(r) : "f"(x)); return r;
}
__device__ __forceinline__ float2 up2(unsigned long long v) {
    float2 r; asm("mov.b64 {%0, %1}, %2;" : "=f"(r.x), "=f"(r.y) : "l"(v)); return r;
}
__device__ __forceinline__ unsigned smem_u32(const void* p) {
    return (unsigned)__cvta_generic_to_shared(p);
}
__device__ __forceinline__ void ld_row10(unsigned addr,
    unsigned long long &m0, unsigned long long &m1, unsigned long long &m2,
    unsigned long long &m3, unsigned long long &m4) {
    asm("{\n\t"
        ".reg .b32 t0,t1,t2,t3,t4,t5,t6,t7,t8,t9;\n\t"
        "ld.shared.v4.b32 {t0,t1,t2,t3}, [%5];\n\t"
        "ld.shared.v4.b32 {t4,t5,t6,t7}, [%5+16];\n\t"
        "ld.shared.v2.b32 {t8,t9}, [%5+32];\n\t"
        "mov.b64 %0, {t0,t1};\n\t"
        "mov.b64 %1, {t2,t3};\n\t"
        "mov.b64 %2, {t4,t5};\n\t"
        "mov.b64 %3, {t6,t7};\n\t"
        "mov.b64 %4, {t8,t9};\n\t"
        "}"
        : "=l"(m0), "=l"(m1), "=l"(m2), "=l"(m3), "=l"(m4) : "r"(addr));
}
__device__ __forceinline__ uint2 ldv2(const uint2* p) {
    uint2 v;
    asm volatile("ld.volatile.global.v2.u32 {%0,%1}, [%2];"
                 : "=r"(v.x), "=r"(v.y) : "l"(p) : "memory");
    return v;
}
__device__ __forceinline__ void stv2(uint2* p, uint2 v) {
    asm volatile("st.volatile.global.v2.u32 [%0], {%1,%2};"
                 :: "l"(p), "r"(v.x), "r"(v.y) : "memory");
}
__device__ __forceinline__ float sig(float x) { return 1.f / (1.f + __expf(-x)); }

// ---------- fused prologue: GEMM (blocks 0-127) + VK (128-147) + zero (148-167) ----------
// OUT[row][c] = E[tok[row]] . [Ww;sk][c] + [Wb;0][c]
__global__ void __launch_bounds__(512) k_pro(const int* __restrict__ ids,
                                             const float* __restrict__ E,
                                             const float* __restrict__ Ww,
                                             const float* __restrict__ Wb,
                                             const float* __restrict__ sk,
                                             const float* __restrict__ Vw,
                                             const float* __restrict__ Vb) {
    int bid = blockIdx.x, tid = threadIdx.x;
    if (bid >= 128) {
        if (bid < 148) {               // Vkey row (bid-128)
            if (tid < 128) {
                int j = bid - 128;
                float acc = Vb[tid];
                const float* skr = sk + j * MEMD;
                const float* vwr = Vw + tid * MEMD;
                #pragma unroll 8
                for (int m = 0; m < MEMD; m++) acc += skr[m] * vwr[m];
                g_VK[j * MEMD + tid] = acc;
            }
        } else {                        // zero g_part: 20 blocks x 512 thr x 8 uint4
            int base = (bid - 148) * 4096 + tid;
            #pragma unroll
            for (int i = 0; i < 8; i++)
                ((uint4*)g_part)[base + i * 512] = make_uint4(0u, 0u, 0u, 0u);
        }
        return;
    }
    __shared__ int   toks[64];
    __shared__ float Ss[64][33];
    __shared__ float Ks[OUTC][33];
    int row0 = bid * 64;
    int tx = tid & 15, ty = tid >> 4;            // tx: 10 cols, ty: 2 rows
    if (tid < 64) {
        int row = row0 + tid;
        toks[tid] = ids[(row >> 7) * 4096 + (row & 127)];
    }
    __syncthreads();
    float acc[2][10];
    #pragma unroll
    for (int i = 0; i < 2; i++)
        #pragma unroll
        for (int j = 0; j < 10; j++) acc[i][j] = 0.f;
    for (int kk = 0; kk < 128; kk += 32) {
        #pragma unroll
        for (int i = 0; i < 4; i++) {
            int idx = tid + i * 512, r = idx >> 5, k = idx & 31;
            float v = E[toks[r] * 128 + kk + k];
            Ss[r][k] = v;
            g_S[(row0 + r) * 128 + kk + k] = v;
        }
        #pragma unroll
        for (int i = 0; i < 10; i++) {
            int idx = tid + i * 512, c = idx >> 5, k = idx & 31;
            float v = 0.f;
            if (c < 128)      v = Ww[c * 128 + kk + k];
            else if (c < 148) v = sk[(c - 128) * 128 + kk + k];
            Ks[c][k] = v;
        }
        __syncthreads();
        #pragma unroll
        for (int k = 0; k < 32; k++) {
            float a[2], bv[10];
            #pragma unroll
            for (int i = 0; i < 2; i++)  a[i]  = Ss[ty * 2 + i][k];
            #pragma unroll
            for (int j = 0; j < 10; j++) bv[j] = Ks[tx * 10 + j][k];
            #pragma unroll
            for (int i = 0; i < 2; i++)
                #pragma unroll
                for (int j = 0; j < 10; j++) acc[i][j] = fmaf(a[i], bv[j], acc[i][j]);
        }
        __syncthreads();
    }
    #pragma unroll
    for (int i = 0; i < 2; i++)
        #pragma unroll
        for (int j = 0; j < 10; j++) {
            int r = row0 + ty * 2 + i, c = tx * 10 + j;
            float bk = (c < 128) ? Wb[c] : 0.f;
            g_O[r * OUTC + c] = acc[i][j] + bk;
        }
}

// ---------- persistent scan: R10 structure + early per-quarter publish ----------
__global__ void __launch_bounds__(512, 1) k_main(const float* __restrict__ Uw,
                                                 const float* __restrict__ Ub) {
    __shared__ float mem_s[128 * RSTR];          // RAW (unnormalized) mem
    __shared__ float vk_s[HSLOT][128];
    __shared__ float s_b[2][128], ws_b[2][128];  // double-buffered staging
    __shared__ float sk_b[2][12];
    __shared__ float red_s[8][5];                // gate partials
    __shared__ float red2_s[16][4];              // sumsq partials per warp
    __shared__ float inv_s[HSLOT];
    __shared__ unsigned long long comb[5][4][128];  // [pair][quarter][n]

    const int tid = threadIdx.x;
    const int n = tid & 127, q = tid >> 7, wid = tid >> 5, lane = tid & 31;
    const int cta = blockIdx.x, b = cta >> 1, half = cta & 1;

    // pre-packed Uw column slice: 32 rows of this thread's k-quarter
    unsigned long long uwr2[32];
    {
        const float4* up = (const float4*)(Uw + n * 128 + q * 32);
        #pragma unroll
        for (int i = 0; i < 8; i++) {
            float4 v = up[i];
            uwr2[4*i]   = pack2(v.x); uwr2[4*i+1] = pack2(v.y);
            uwr2[4*i+2] = pack2(v.z); uwr2[4*i+3] = pack2(v.w);
        }
    }
    const float ubn = Ub[n];
    for (int idx = tid; idx < HSLOT * 128; idx += 512)
        vk_s[idx >> 7][idx & 127] = g_VK[(half * HSLOT + (idx >> 7)) * 128 + (idx & 127)];
    for (int idx = tid; idx < 128 * RSTR; idx += 512) mem_s[idx] = 0.f;

    float memv[4];
    #pragma unroll
    for (int i = 0; i < 4; i++) memv[i] = 0.f;

    const float* Sb = g_S + b * 128 * 128;
    const float* Ob = g_O + b * 128 * OUTC;
    if (q == 0) { s_b[0][n] = Sb[n]; ws_b[0][n] = Ob[n]; }
    else if (q == 1 && n < HSLOT) sk_b[0][n] = Ob[128 + half * HSLOT + n];
    if (tid < HSLOT) inv_s[tid] = 1.f;           // t=0: mem is exactly zero
    __syncthreads();

    const unsigned mem_u32 = smem_u32(mem_s) + q * 32 * (RSTR * 4);

    for (int t = 0; t < NSTEP; t++) {
        const int cur = t & 1, nxt = cur ^ 1;

        // ---- A. q0/q1: staging prefetch; q2/q3: raw gate dots ----
        float s_nxt = 0.f, ws_nxt = 0.f, skey_nxt = 0.f;
        if (q < 2) {
            int tn = (t + 1) & 127;
            if (q == 0) { s_nxt = Sb[tn * 128 + n]; ws_nxt = Ob[tn * OUTC + n]; }
            else if (n < HSLOT) skey_nxt = Ob[tn * OUTC + 128 + half * HSLOT + n];
        } else {
            float sv = s_b[cur][n];
            const float* row = mem_s + n * RSTR + (q - 2) * 5;
            float p0 = sv * row[0], p1 = sv * row[1], p2 = sv * row[2];
            float p3 = sv * row[3], p4 = sv * row[4];
            #pragma unroll
            for (int s = 16; s; s >>= 1) {
                p0 += __shfl_xor_sync(~0u, p0, s);
                p1 += __shfl_xor_sync(~0u, p1, s);
                p2 += __shfl_xor_sync(~0u, p2, s);
                p3 += __shfl_xor_sync(~0u, p3, s);
                p4 += __shfl_xor_sync(~0u, p4, s);
            }
            if (lane == 0) {
                float* rr = red_s[wid - 8];
                rr[0] = p0; rr[1] = p1; rr[2] = p2; rr[3] = p3; rr[4] = p4;
            }
        }

        // ---- B. matmul quarter: 32 rows x (3 LDS + 5 FFMA2) ----
        unsigned long long accv[5];
        #pragma unroll
        for (int p = 0; p < 5; p++) accv[p] = 0ull;
        #pragma unroll
        for (int k = 0; k < 32; k++) {
            unsigned long long m0, m1, m2, m3, m4;
            ld_row10(mem_u32 + k * (RSTR * 4), m0, m1, m2, m3, m4);
            ffma2(accv[0], uwr2[k], m0);
            ffma2(accv[1], uwr2[k], m1);
            ffma2(accv[2], uwr2[k], m2);
            ffma2(accv[3], uwr2[k], m3);
            ffma2(accv[4], uwr2[k], m4);
        }
        #pragma unroll
        for (int p = 0; p < 5; p++) comb[p][q][n] = accv[p];

        // ---- C. poll norms (warps 0-4, per-thread independent exit) ----
        if (t && wid < 5) {
            int j = tid >> 4, i = tid & 15;
            const uint2* pp = &g_part[t - 1][half * HSLOT + j][i];
            const unsigned want = (unsigned)t;
            uint2 v0 = ldv2(pp), v1 = ldv2(pp + 16), v2 = ldv2(pp + 32), v3 = ldv2(pp + 48);
            while ((v0.y ^ want) | (v1.y ^ want) | (v2.y ^ want) | (v3.y ^ want)) {
                v0 = ldv2(pp); v1 = ldv2(pp + 16); v2 = ldv2(pp + 32); v3 = ldv2(pp + 48);
            }
            float acc = __uint_as_float(v0.x) + __uint_as_float(v1.x)
                      + __uint_as_float(v2.x) + __uint_as_float(v3.x);
            acc += __shfl_xor_sync(~0u, acc, 8);
            acc += __shfl_xor_sync(~0u, acc, 4);
            acc += __shfl_xor_sync(~0u, acc, 2);
            acc += __shfl_xor_sync(~0u, acc, 1);
            if (i == 0) inv_s[j] = rsqrtf(acc);
        }
        __syncthreads();   // comb + red_s + inv_s all visible

        // ---- D. epilogue: combine quarters, gate, relu, update, sumsq ----
        const float wsv = ws_b[cur][n];
        float* row = mem_s + n * RSTR;
        const unsigned tagp = (unsigned)(t + 1);
        if (q == 0) {
            float sq[4];
            #pragma unroll
            for (int p = 0; p < 2; p++) {
                unsigned long long tot = add2(add2(comb[p][0][n], comb[p][1][n]),
                                              add2(comb[p][2][n], comb[p][3][n]));
                float2 a = up2(tot);
                const int j0 = 2 * p, j1 = 2 * p + 1;
                float r0 = red_s[0][j0] + red_s[1][j0] + red_s[2][j0] + red_s[3][j0];
                float r1 = red_s[0][j1] + red_s[1][j1] + red_s[2][j1] + red_s[3][j1];
                float i0 = inv_s[j0], i1 = inv_s[j1];
                float g0 = sig(fmaf(i0, r0, sk_b[cur][j0]));
                float g1 = sig(fmaf(i1, r1, sk_b[cur][j1]));
                float h0 = fmaxf(fmaf(i0, a.x, ubn + vk_s[j0][n] + wsv), 0.f);
                float h1 = fmaxf(fmaf(i1, a.y, ubn + vk_s[j1][n] + wsv), 0.f);
                memv[j0] = fmaf(memv[j0], i0, g0 * h0);
                memv[j1] = fmaf(memv[j1], i1, g1 * h1);
                sq[j0] = memv[j0] * memv[j0];
                sq[j1] = memv[j1] * memv[j1];
            }
            #pragma unroll
            for (int s = 16; s; s >>= 1)
                #pragma unroll
                for (int i = 0; i < 4; i++) sq[i] += __shfl_xor_sync(~0u, sq[i], s);
            if (lane == 0) {
                red2_s[wid][0] = sq[0]; red2_s[wid][1] = sq[1];
                red2_s[wid][2] = sq[2]; red2_s[wid][3] = sq[3];
            }
            *(float4*)row = make_float4(memv[0], memv[1], memv[2], memv[3]);
            s_b[nxt][n] = s_nxt; ws_b[nxt][n] = ws_nxt;
            // early publish: quarter-local barrier, then warp 0 lanes 0-3 publish slots 0-3
            asm volatile("bar.sync 1, 128;" ::: "memory");
            if (wid == 0 && lane < 4) {
                float v = red2_s[0][lane] + red2_s[1][lane] + red2_s[2][lane] + red2_s[3][lane];
                uint2 pkt; pkt.x = __float_as_uint(v); pkt.y = tagp;
                stv2(&g_part[t][half * HSLOT + lane][b], pkt);
            }
        } else {
            const int p = q + 1;                 // pair owned: q1->2, q2->3, q3->4
            const int j0 = 2 * p, j1 = 2 * p + 1;
            unsigned long long tot = add2(add2(comb[p][0][n], comb[p][1][n]),
                                          add2(comb[p][2][n], comb[p][3][n]));
            float2 a = up2(tot);
            float r0 = (j0 < 5) ? red_s[0][j0] + red_s[1][j0] + red_s[2][j0] + red_s[3][j0]
                                : red_s[4][j0-5] + red_s[5][j0-5] + red_s[6][j0-5] + red_s[7][j0-5];
            float r1 = (j1 < 5) ? red_s[0][j1] + red_s[1][j1] + red_s[2][j1] + red_s[3][j1]
                                : red_s[4][j1-5] + red_s[5][j1-5] + red_s[6][j1-5] + red_s[7][j1-5];
            float i0 = inv_s[j0], i1 = inv_s[j1];
            float g0 = sig(fmaf(i0, r0, sk_b[cur][j0]));
            float g1 = sig(fmaf(i1, r1, sk_b[cur][j1]));
            float h0 = fmaxf(fmaf(i0, a.x, ubn + vk_s[j0][n] + wsv), 0.f);
            float h1 = fmaxf(fmaf(i1, a.y, ubn + vk_s[j1][n] + wsv), 0.f);
            memv[0] = fmaf(memv[0], i0, g0 * h0);
            memv[1] = fmaf(memv[1], i1, g1 * h1);
            float sq0 = memv[0] * memv[0], sq1 = memv[1] * memv[1];
            #pragma unroll
            for (int s = 16; s; s >>= 1) {
                sq0 += __shfl_xor_sync(~0u, sq0, s);
                sq1 += __shfl_xor_sync(~0u, sq1, s);
            }
            if (lane == 0) { red2_s[wid][0] = sq0; red2_s[wid][1] = sq1; }
            *(float2*)(row + j0) = make_float2(memv[0], memv[1]);
            if (q == 1 && n < HSLOT) sk_b[nxt][n] = skey_nxt;
            // early publish: quarter-local barrier, then first warp of quarter publishes 2 slots
            if (q == 1)      asm volatile("bar.sync 2, 128;" ::: "memory");
            else if (q == 2) asm volatile("bar.sync 3, 128;" ::: "memory");
            else             asm volatile("bar.sync 4, 128;" ::: "memory");
            if ((wid & 3) == 0 && lane < 2) {
                int w0 = q * 4;
                float v = red2_s[w0][lane] + red2_s[w0+1][lane]
                        + red2_s[w0+2][lane] + red2_s[w0+3][lane];
                uint2 pkt; pkt.x = __float_as_uint(v); pkt.y = tagp;
                stv2(&g_part[t][half * HSLOT + j0 + lane][b], pkt);
            }
        }
        __syncthreads();   // mem(t+1) + staging visible for next step
    }

    // ---- final normalization ----
    if (wid < 5) {
        int j = tid >> 4, i = tid & 15;
        const uint2* pp = &g_part[NSTEP - 1][half * HSLOT + j][i];
        const unsigned want = (unsigned)NSTEP;
        uint2 v0 = ldv2(pp), v1 = ldv2(pp + 16), v2 = ldv2(pp + 32), v3 = ldv2(pp + 48);
        while ((v0.y ^ want) | (v1.y ^ want) | (v2.y ^ want) | (v3.y ^ want)) {
            v0 = ldv2(pp); v1 = ldv2(pp + 16); v2 = ldv2(pp + 32); v3 = ldv2(pp + 48);
        }
        float acc = __uint_as_float(v0.x) + __uint_as_float(v1.x)
                  + __uint_as_float(v2.x) + __uint_as_float(v3.x);
        acc += __shfl_xor_sync(~0u, acc, 8);
        acc += __shfl_xor_sync(~0u, acc, 4);
        acc += __shfl_xor_sync(~0u, acc, 2);
        acc += __shfl_xor_sync(~0u, acc, 1);
        if (i == 0) inv_s[j] = rsqrtf(acc);
    }
    __syncthreads();

    {
        float* gh = g_H + b * (NSLOT * MEMD) + half * HSLOT * MEMD;
        if (q == 0) {
            #pragma unroll
            for (int j = 0; j < 4; j++) gh[j * MEMD + n] = memv[j] * inv_s[j];
        } else {
            const int j0 = 2 * (q + 1);
            gh[j0 * MEMD + n]       = memv[0] * inv_s[j0];
            gh[(j0 + 1) * MEMD + n] = memv[1] * inv_s[j0 + 1];
        }
    }
}

// ---------- epilogue ----------
__global__ void k_epi(const int* __restrict__ q, const int* __restrict__ ans,
                      const float* __restrict__ E, const float* __restrict__ Hw,
                      const float* __restrict__ Hb, float* __restrict__ out) {
    __shared__ float red[4][NSLOT];
    __shared__ float p_s[NSLOT];
    __shared__ __align__(16) float u_s[MEMD];
    __shared__ float yr[4][2];
    int b = blockIdx.x, n = threadIdx.x, w = n >> 5, l = n & 31;

    float qv = 0.f;
    #pragma unroll
    for (int i = 0; i < 16; i++) qv += E[q[b * 16 + i] * MEMD + n];
    qv *= (1.f / 16.f);
    float a1 = 0.f, a2 = 0.f;
    #pragma unroll
    for (int i = 0; i < 8; i++) {
        a1 += E[ans[(b * 8 + i) * 2 + 0] * MEMD + n];
        a2 += E[ans[(b * 8 + i) * 2 + 1] * MEMD + n];
    }
    a1 *= 0.125f; a2 *= 0.125f;

    float hv[NSLOT], p[NSLOT];
    #pragma unroll
    for (int jj = 0; jj < NSLOT; jj++) {
        hv[jj] = g_H[b * (NSLOT * MEMD) + jj * MEMD + n];
        p[jj] = hv[jj] * qv;
    }
    #pragma unroll
    for (int s = 16; s; s >>= 1)
        #pragma unroll
        for (int jj = 0; jj < NSLOT; jj++) p[jj] += __shfl_xor_sync(~0u, p[jj], s);
    if (l == 0) {
        #pragma unroll
        for (int jj = 0; jj < NSLOT; jj++) red[w][jj] = p[jj];
    }
    __syncthreads();
    if (n == 0) {
        float d[NSLOT], mx = -1e30f;
        #pragma unroll
        for (int jj = 0; jj < NSLOT; jj++) {
            d[jj] = red[0][jj] + red[1][jj] + red[2][jj] + red[3][jj];
            mx = fmaxf(mx, d[jj]);
        }
        float sm = 0.f;
        #pragma unroll
        for (int jj = 0; jj < NSLOT; jj++) { d[jj] = expf(d[jj] - mx); sm += d[jj]; }
        float inv = 1.f / sm;
        #pragma unroll
        for (int jj = 0; jj < NSLOT; jj++) p_s[jj] = d[jj] * inv;
    }
    __syncthreads();

    float u = 0.f;
    #pragma unroll
    for (int jj = 0; jj < NSLOT; jj++) u = fmaf(p_s[jj], hv[jj], u);
    u_s[n] = u;
    __syncthreads();

    // Hw matvec: 4 independent FMA chains, float4 loads
    float r0 = 0.f, r1 = 0.f, r2 = 0.f, r3 = 0.f;
    const float4* hw4 = (const float4*)(Hw + n * MEMD);
    const float4* u4  = (const float4*)u_s;
    #pragma unroll
    for (int i = 0; i < 32; i += 4) {
        float4 h0 = hw4[i],     x0 = u4[i];
        float4 h1 = hw4[i + 1], x1 = u4[i + 1];
        float4 h2 = hw4[i + 2], x2 = u4[i + 2];
        float4 h3 = hw4[i + 3], x3 = u4[i + 3];
        r0 = fmaf(x0.x, h0.x, fmaf(x0.y, h0.y, fmaf(x0.z, h0.z, fmaf(x0.w, h0.w, r0))));
        r1 = fmaf(x1.x, h1.x, fmaf(x1.y, h1.y, fmaf(x1.z, h1.z, fmaf(x1.w, h1.w, r1))));
        r2 = fmaf(x2.x, h2.x, fmaf(x2.y, h2.y, fmaf(x2.z, h2.z, fmaf(x2.w, h2.w, r2))));
        r3 = fmaf(x3.x, h3.x, fmaf(x3.y, h3.y, fmaf(x3.z, h3.z, fmaf(x3.w, h3.w, r3))));
    }
    float r = fmaxf(qv + Hb[n] + ((r0 + r1) + (r2 + r3)), 0.f);

    float y1 = r * a1, y2 = r * a2;
    #pragma unroll
    for (int s = 16; s; s >>= 1) {
        y1 += __shfl_xor_sync(~0u, y1, s);
        y2 += __shfl_xor_sync(~0u, y2, s);
    }
    if (l == 0) { yr[w][0] = y1; yr[w][1] = y2; }
    __syncthreads();
    if (n == 0) {
        float s1 = yr[0][0] + yr[1][0] + yr[2][0] + yr[3][0];
        float s2 = yr[0][1] + yr[1][1] + yr[2][1] + yr[3][1];
        float mx = fmaxf(s1, s2);
        float e1 = expf(s1 - mx), e2 = expf(s2 - mx);
        float inv = 1.f / (e1 + e2);
        out[b * 2 + 0] = e1 * inv;
        out[b * 2 + 1] = e2 * inv;
    }
}

extern "C" void kernel_launch(void* const* d_in, const int* in_sizes, int n_in,
                              void* d_out, int out_size) {
    const int*   input_ids = (const int*)  d_in[0];
    const int*   question  = (const int*)  d_in[1];
    const int*   ans       = (const int*)  d_in[2];
    const float* E         = (const float*)d_in[3];
    const float* Uw        = (const float*)d_in[4];
    const float* Ub        = (const float*)d_in[5];
    const float* Vw        = (const float*)d_in[6];
    const float* Vb        = (const float*)d_in[7];
    const float* Ww        = (const float*)d_in[8];
    const float* Wb        = (const float*)d_in[9];
    const float* sk        = (const float*)d_in[10];
    const float* Hw        = (const float*)d_in[11];
    const float* Hb        = (const float*)d_in[12];
    float* out = (float*)d_out;

    k_pro  <<<168, 512>>>(input_ids, E, Ww, Wb, sk, Vw, Vb);
    k_main <<<NCTA, 512>>>(Uw, Ub);
    k_epi  <<<64, 128>>>(question, ans, E, Hw, Hb, out);
}

// round 13
// speedup vs baseline: 1.0888x; 1.0055x over previous
#include <cuda_runtime.h>
#include <math.h>

#define NBATCH 64
#define NSTEP  128
#define MEMD   128
#define NSLOT  20
#define HSLOT  10
#define NCTA   128
#define OUTC   160
#define RSTR   12      // floats per mem_s row (48B, 16B aligned)

__device__ float g_S [NBATCH * NSTEP * MEMD];
__device__ float g_O [NBATCH * NSTEP * OUTC];
__device__ float g_VK[NSLOT * MEMD];
__device__ uint2 g_part[NSTEP][NSLOT][NBATCH];   // {value bits, tag = t+1}
__device__ float g_H [NBATCH * NSLOT * MEMD];

// ---------- helpers ----------
__device__ __forceinline__ void ffma2(unsigned long long &acc, unsigned long long a,
                                      unsigned long long b) {
    asm("fma.rn.f32x2 %0, %1, %2, %0;" : "+l"(acc) : "l"(a), "l"(b));
}
__device__ __forceinline__ unsigned long long add2(unsigned long long a,
                                                   unsigned long long b) {
    unsigned long long r;
    asm("add.rn.f32x2 %0, %1, %2;" : "=l"(r) : "l"(a), "l"(b));
    return r;
}
__device__ __forceinline__ unsigned long long pack2(float x) {
    unsigned long long r; asm("mov.b64 %0, {%1, %1};" : "=l"(r) : "f"(x)); return r;
}
__device__ __forceinline__ float2 up2(unsigned long long v) {
    float2 r; asm("mov.b64 {%0, %1}, %2;" : "=f"(r.x), "=f"(r.y) : "l"(v)); return r;
}
__device__ __forceinline__ unsigned smem_u32(const void* p) {
    return (unsigned)__cvta_generic_to_shared(p);
}
__device__ __forceinline__ void ld_row10(unsigned addr,
    unsigned long long &m0, unsigned long long &m1, unsigned long long &m2,
    unsigned long long &m3, unsigned long long &m4) {
    asm("{\n\t"
        ".reg .b32 t0,t1,t2,t3,t4,t5,t6,t7,t8,t9;\n\t"
        "ld.shared.v4.b32 {t0,t1,t2,t3}, [%5];\n\t"
        "ld.shared.v4.b32 {t4,t5,t6,t7}, [%5+16];\n\t"
        "ld.shared.v2.b32 {t8,t9}, [%5+32];\n\t"
        "mov.b64 %0, {t0,t1};\n\t"
        "mov.b64 %1, {t2,t3};\n\t"
        "mov.b64 %2, {t4,t5};\n\t"
        "mov.b64 %3, {t6,t7};\n\t"
        "mov.b64 %4, {t8,t9};\n\t"
        "}"
        : "=l"(m0), "=l"(m1), "=l"(m2), "=l"(m3), "=l"(m4) : "r"(addr));
}
__device__ __forceinline__ uint2 ldv2(const uint2* p) {
    uint2 v;
    asm volatile("ld.volatile.global.v2.u32 {%0,%1}, [%2];"
                 : "=r"(v.x), "=r"(v.y) : "l"(p) : "memory");
    return v;
}
__device__ __forceinline__ void stv2(uint2* p, uint2 v) {
    asm volatile("st.volatile.global.v2.u32 [%0], {%1,%2};"
                 :: "l"(p), "r"(v.x), "r"(v.y) : "memory");
}
__device__ __forceinline__ float sig(float x) { return 1.f / (1.f + __expf(-x)); }

// ---------- fused prologue (256 thr): GEMM blocks 0-127 + VK 128-147 + zero 148-187 ----------
// OUT[row][c] = E[tok[row]] . [Ww;sk][c] + [Wb;0][c]
__global__ void __launch_bounds__(256) k_pro(const int* __restrict__ ids,
                                             const float* __restrict__ E,
                                             const float* __restrict__ Ww,
                                             const float* __restrict__ Wb,
                                             const float* __restrict__ sk,
                                             const float* __restrict__ Vw,
                                             const float* __restrict__ Vb) {
    int bid = blockIdx.x, tid = threadIdx.x;
    if (bid >= 128) {
        if (bid < 148) {               // Vkey row (bid-128)
            if (tid < 128) {
                int j = bid - 128;
                float acc = Vb[tid];
                const float* skr = sk + j * MEMD;
                const float* vwr = Vw + tid * MEMD;
                #pragma unroll 8
                for (int m = 0; m < MEMD; m++) acc += skr[m] * vwr[m];
                g_VK[j * MEMD + tid] = acc;
            }
        } else {                        // zero g_part: 40 blocks x 256 thr x 8 uint4
            int base = (bid - 148) * 2048 + tid;
            #pragma unroll
            for (int i = 0; i < 8; i++)
                ((uint4*)g_part)[base + i * 256] = make_uint4(0u, 0u, 0u, 0u);
        }
        return;
    }
    __shared__ int   toks[64];
    __shared__ float Ss[64][33];
    __shared__ float Ks[OUTC][33];
    int row0 = bid * 64;
    int tx = tid & 15, ty = tid >> 4;            // tx: 10 cols, ty: 4 rows
    if (tid < 64) {
        int row = row0 + tid;
        toks[tid] = ids[(row >> 7) * 4096 + (row & 127)];
    }
    __syncthreads();
    float acc[4][10];
    #pragma unroll
    for (int i = 0; i < 4; i++)
        #pragma unroll
        for (int j = 0; j < 10; j++) acc[i][j] = 0.f;
    for (int kk = 0; kk < 128; kk += 32) {
        #pragma unroll
        for (int i = 0; i < 8; i++) {
            int idx = tid + i * 256, r = idx >> 5, k = idx & 31;
            float v = E[toks[r] * 128 + kk + k];
            Ss[r][k] = v;
            g_S[(row0 + r) * 128 + kk + k] = v;
        }
        #pragma unroll
        for (int i = 0; i < 20; i++) {
            int idx = tid + i * 256, c = idx >> 5, k = idx & 31;
            float v = 0.f;
            if (c < 128)      v = Ww[c * 128 + kk + k];
            else if (c < 148) v = sk[(c - 128) * 128 + kk + k];
            Ks[c][k] = v;
        }
        __syncthreads();
        #pragma unroll
        for (int k = 0; k < 32; k++) {
            float a[4], bv[10];
            #pragma unroll
            for (int i = 0; i < 4; i++)  a[i]  = Ss[ty * 4 + i][k];
            #pragma unroll
            for (int j = 0; j < 10; j++) bv[j] = Ks[tx * 10 + j][k];
            #pragma unroll
            for (int i = 0; i < 4; i++)
                #pragma unroll
                for (int j = 0; j < 10; j++) acc[i][j] = fmaf(a[i], bv[j], acc[i][j]);
        }
        __syncthreads();
    }
    #pragma unroll
    for (int i = 0; i < 4; i++)
        #pragma unroll
        for (int j = 0; j < 10; j++) {
            int r = row0 + ty * 4 + i, c = tx * 10 + j;
            float bk = (c < 128) ? Wb[c] : 0.f;
            g_O[r * OUTC + c] = acc[i][j] + bk;
        }
}

// ---------- persistent scan: R12 + publish-first epilogue ----------
__global__ void __launch_bounds__(512, 1) k_main(const float* __restrict__ Uw,
                                                 const float* __restrict__ Ub) {
    __shared__ float mem_s[128 * RSTR];          // RAW (unnormalized) mem
    __shared__ float vk_s[HSLOT][128];
    __shared__ float s_b[2][128], ws_b[2][128];  // double-buffered staging
    __shared__ float sk_b[2][12];
    __shared__ float red_s[8][5];                // gate partials
    __shared__ float red2_s[16][4];              // sumsq partials per warp
    __shared__ float inv_s[HSLOT];
    __shared__ unsigned long long comb[5][4][128];  // [pair][quarter][n]

    const int tid = threadIdx.x;
    const int n = tid & 127, q = tid >> 7, wid = tid >> 5, lane = tid & 31;
    const int cta = blockIdx.x, b = cta >> 1, half = cta & 1;

    // pre-packed Uw column slice: 32 rows of this thread's k-quarter
    unsigned long long uwr2[32];
    {
        const float4* up = (const float4*)(Uw + n * 128 + q * 32);
        #pragma unroll
        for (int i = 0; i < 8; i++) {
            float4 v = up[i];
            uwr2[4*i]   = pack2(v.x); uwr2[4*i+1] = pack2(v.y);
            uwr2[4*i+2] = pack2(v.z); uwr2[4*i+3] = pack2(v.w);
        }
    }
    const float ubn = Ub[n];
    for (int idx = tid; idx < HSLOT * 128; idx += 512)
        vk_s[idx >> 7][idx & 127] = g_VK[(half * HSLOT + (idx >> 7)) * 128 + (idx & 127)];
    for (int idx = tid; idx < 128 * RSTR; idx += 512) mem_s[idx] = 0.f;

    float memv[4];
    #pragma unroll
    for (int i = 0; i < 4; i++) memv[i] = 0.f;

    const float* Sb = g_S + b * 128 * 128;
    const float* Ob = g_O + b * 128 * OUTC;
    if (q == 0) { s_b[0][n] = Sb[n]; ws_b[0][n] = Ob[n]; }
    else if (q == 1 && n < HSLOT) sk_b[0][n] = Ob[128 + half * HSLOT + n];
    if (tid < HSLOT) inv_s[tid] = 1.f;           // t=0: mem is exactly zero
    __syncthreads();

    const unsigned mem_u32 = smem_u32(mem_s) + q * 32 * (RSTR * 4);

    for (int t = 0; t < NSTEP; t++) {
        const int cur = t & 1, nxt = cur ^ 1;

        // ---- A. q0/q1: staging prefetch; q2/q3: raw gate dots ----
        float s_nxt = 0.f, ws_nxt = 0.f, skey_nxt = 0.f;
        if (q < 2) {
            int tn = (t + 1) & 127;
            if (q == 0) { s_nxt = Sb[tn * 128 + n]; ws_nxt = Ob[tn * OUTC + n]; }
            else if (n < HSLOT) skey_nxt = Ob[tn * OUTC + 128 + half * HSLOT + n];
        } else {
            float sv = s_b[cur][n];
            const float* row = mem_s + n * RSTR + (q - 2) * 5;
            float p0 = sv * row[0], p1 = sv * row[1], p2 = sv * row[2];
            float p3 = sv * row[3], p4 = sv * row[4];
            #pragma unroll
            for (int s = 16; s; s >>= 1) {
                p0 += __shfl_xor_sync(~0u, p0, s);
                p1 += __shfl_xor_sync(~0u, p1, s);
                p2 += __shfl_xor_sync(~0u, p2, s);
                p3 += __shfl_xor_sync(~0u, p3, s);
                p4 += __shfl_xor_sync(~0u, p4, s);
            }
            if (lane == 0) {
                float* rr = red_s[wid - 8];
                rr[0] = p0; rr[1] = p1; rr[2] = p2; rr[3] = p3; rr[4] = p4;
            }
        }

        // ---- B. matmul quarter: 32 rows x (3 LDS + 5 FFMA2) ----
        unsigned long long accv[5];
        #pragma unroll
        for (int p = 0; p < 5; p++) accv[p] = 0ull;
        #pragma unroll
        for (int k = 0; k < 32; k++) {
            unsigned long long m0, m1, m2, m3, m4;
            ld_row10(mem_u32 + k * (RSTR * 4), m0, m1, m2, m3, m4);
            ffma2(accv[0], uwr2[k], m0);
            ffma2(accv[1], uwr2[k], m1);
            ffma2(accv[2], uwr2[k], m2);
            ffma2(accv[3], uwr2[k], m3);
            ffma2(accv[4], uwr2[k], m4);
        }
        #pragma unroll
        for (int p = 0; p < 5; p++) comb[p][q][n] = accv[p];

        // ---- C. poll norms (warps 0-4, per-thread independent exit) ----
        if (t && wid < 5) {
            int j = tid >> 4, i = tid & 15;
            const uint2* pp = &g_part[t - 1][half * HSLOT + j][i];
            const unsigned want = (unsigned)t;
            uint2 v0 = ldv2(pp), v1 = ldv2(pp + 16), v2 = ldv2(pp + 32), v3 = ldv2(pp + 48);
            while ((v0.y ^ want) | (v1.y ^ want) | (v2.y ^ want) | (v3.y ^ want)) {
                v0 = ldv2(pp); v1 = ldv2(pp + 16); v2 = ldv2(pp + 32); v3 = ldv2(pp + 48);
            }
            float acc = __uint_as_float(v0.x) + __uint_as_float(v1.x)
                      + __uint_as_float(v2.x) + __uint_as_float(v3.x);
            acc += __shfl_xor_sync(~0u, acc, 8);
            acc += __shfl_xor_sync(~0u, acc, 4);
            acc += __shfl_xor_sync(~0u, acc, 2);
            acc += __shfl_xor_sync(~0u, acc, 1);
            if (i == 0) inv_s[j] = rsqrtf(acc);
        }
        __syncthreads();   // comb + red_s + inv_s all visible

        // ---- D. epilogue: publish path FIRST, mem/staging writes after ----
        const float wsv = ws_b[cur][n];
        float* row = mem_s + n * RSTR;
        const unsigned tagp = (unsigned)(t + 1);
        if (q == 0) {
            float sq[4];
            #pragma unroll
            for (int p = 0; p < 2; p++) {
                unsigned long long tot = add2(add2(comb[p][0][n], comb[p][1][n]),
                                              add2(comb[p][2][n], comb[p][3][n]));
                float2 a = up2(tot);
                const int j0 = 2 * p, j1 = 2 * p + 1;
                float r0 = red_s[0][j0] + red_s[1][j0] + red_s[2][j0] + red_s[3][j0];
                float r1 = red_s[0][j1] + red_s[1][j1] + red_s[2][j1] + red_s[3][j1];
                float i0 = inv_s[j0], i1 = inv_s[j1];
                float g0 = sig(fmaf(i0, r0, sk_b[cur][j0]));
                float g1 = sig(fmaf(i1, r1, sk_b[cur][j1]));
                float h0 = fmaxf(fmaf(i0, a.x, ubn + vk_s[j0][n] + wsv), 0.f);
                float h1 = fmaxf(fmaf(i1, a.y, ubn + vk_s[j1][n] + wsv), 0.f);
                memv[j0] = fmaf(memv[j0], i0, g0 * h0);
                memv[j1] = fmaf(memv[j1], i1, g1 * h1);
                sq[j0] = memv[j0] * memv[j0];
                sq[j1] = memv[j1] * memv[j1];
            }
            #pragma unroll
            for (int s = 16; s; s >>= 1)
                #pragma unroll
                for (int i = 0; i < 4; i++) sq[i] += __shfl_xor_sync(~0u, sq[i], s);
            if (lane == 0) {
                red2_s[wid][0] = sq[0]; red2_s[wid][1] = sq[1];
                red2_s[wid][2] = sq[2]; red2_s[wid][3] = sq[3];
            }
            asm volatile("bar.sync 1, 128;" ::: "memory");
            if (wid == 0 && lane < 4) {
                float v = red2_s[0][lane] + red2_s[1][lane] + red2_s[2][lane] + red2_s[3][lane];
                uint2 pkt; pkt.x = __float_as_uint(v); pkt.y = tagp;
                stv2(&g_part[t][half * HSLOT + lane][b], pkt);
            }
            // deferred writes (guarded by step-final __syncthreads)
            *(float4*)row = make_float4(memv[0], memv[1], memv[2], memv[3]);
            s_b[nxt][n] = s_nxt; ws_b[nxt][n] = ws_nxt;
        } else {
            const int p = q + 1;                 // pair owned: q1->2, q2->3, q3->4
            const int j0 = 2 * p, j1 = 2 * p + 1;
            unsigned long long tot = add2(add2(comb[p][0][n], comb[p][1][n]),
                                          add2(comb[p][2][n], comb[p][3][n]));
            float2 a = up2(tot);
            float r0 = (j0 < 5) ? red_s[0][j0] + red_s[1][j0] + red_s[2][j0] + red_s[3][j0]
                                : red_s[4][j0-5] + red_s[5][j0-5] + red_s[6][j0-5] + red_s[7][j0-5];
            float r1 = (j1 < 5) ? red_s[0][j1] + red_s[1][j1] + red_s[2][j1] + red_s[3][j1]
                                : red_s[4][j1-5] + red_s[5][j1-5] + red_s[6][j1-5] + red_s[7][j1-5];
            float i0 = inv_s[j0], i1 = inv_s[j1];
            float g0 = sig(fmaf(i0, r0, sk_b[cur][j0]));
            float g1 = sig(fmaf(i1, r1, sk_b[cur][j1]));
            float h0 = fmaxf(fmaf(i0, a.x, ubn + vk_s[j0][n] + wsv), 0.f);
            float h1 = fmaxf(fmaf(i1, a.y, ubn + vk_s[j1][n] + wsv), 0.f);
            memv[0] = fmaf(memv[0], i0, g0 * h0);
            memv[1] = fmaf(memv[1], i1, g1 * h1);
            float sq0 = memv[0] * memv[0], sq1 = memv[1] * memv[1];
            #pragma unroll
            for (int s = 16; s; s >>= 1) {
                sq0 += __shfl_xor_sync(~0u, sq0, s);
                sq1 += __shfl_xor_sync(~0u, sq1, s);
            }
            if (lane == 0) { red2_s[wid][0] = sq0; red2_s[wid][1] = sq1; }
            if (q == 1)      asm volatile("bar.sync 2, 128;" ::: "memory");
            else if (q == 2) asm volatile("bar.sync 3, 128;" ::: "memory");
            else             asm volatile("bar.sync 4, 128;" ::: "memory");
            if ((wid & 3) == 0 && lane < 2) {
                int w0 = q * 4;
                float v = red2_s[w0][lane] + red2_s[w0+1][lane]
                        + red2_s[w0+2][lane] + red2_s[w0+3][lane];
                uint2 pkt; pkt.x = __float_as_uint(v); pkt.y = tagp;
                stv2(&g_part[t][half * HSLOT + j0 + lane][b], pkt);
            }
            // deferred writes
            *(float2*)(row + j0) = make_float2(memv[0], memv[1]);
            if (q == 1 && n < HSLOT) sk_b[nxt][n] = skey_nxt;
        }
        __syncthreads();   // mem(t+1) + staging visible for next step
    }

    // ---- final normalization ----
    if (wid < 5) {
        int j = tid >> 4, i = tid & 15;
        const uint2* pp = &g_part[NSTEP - 1][half * HSLOT + j][i];
        const unsigned want = (unsigned)NSTEP;
        uint2 v0 = ldv2(pp), v1 = ldv2(pp + 16), v2 = ldv2(pp + 32), v3 = ldv2(pp + 48);
        while ((v0.y ^ want) | (v1.y ^ want) | (v2.y ^ want) | (v3.y ^ want)) {
            v0 = ldv2(pp); v1 = ldv2(pp + 16); v2 = ldv2(pp + 32); v3 = ldv2(pp + 48);
        }
        float acc = __uint_as_float(v0.x) + __uint_as_float(v1.x)
                  + __uint_as_float(v2.x) + __uint_as_float(v3.x);
        acc += __shfl_xor_sync(~0u, acc, 8);
        acc += __shfl_xor_sync(~0u, acc, 4);
        acc += __shfl_xor_sync(~0u, acc, 2);
        acc += __shfl_xor_sync(~0u, acc, 1);
        if (i == 0) inv_s[j] = rsqrtf(acc);
    }
    __syncthreads();

    {
        float* gh = g_H + b * (NSLOT * MEMD) + half * HSLOT * MEMD;
        if (q == 0) {
            #pragma unroll
            for (int j = 0; j < 4; j++) gh[j * MEMD + n] = memv[j] * inv_s[j];
        } else {
            const int j0 = 2 * (q + 1);
            gh[j0 * MEMD + n]       = memv[0] * inv_s[j0];
            gh[(j0 + 1) * MEMD + n] = memv[1] * inv_s[j0 + 1];
        }
    }
}

// ---------- epilogue ----------
__global__ void k_epi(const int* __restrict__ q, const int* __restrict__ ans,
                      const float* __restrict__ E, const float* __restrict__ Hw,
                      const float* __restrict__ Hb, float* __restrict__ out) {
    __shared__ float red[4][NSLOT];
    __shared__ float p_s[NSLOT];
    __shared__ __align__(16) float u_s[MEMD];
    __shared__ float yr[4][2];
    int b = blockIdx.x, n = threadIdx.x, w = n >> 5, l = n & 31;

    float qv = 0.f;
    #pragma unroll
    for (int i = 0; i < 16; i++) qv += E[q[b * 16 + i] * MEMD + n];
    qv *= (1.f / 16.f);
    float a1 = 0.f, a2 = 0.f;
    #pragma unroll
    for (int i = 0; i < 8; i++) {
        a1 += E[ans[(b * 8 + i) * 2 + 0] * MEMD + n];
        a2 += E[ans[(b * 8 + i) * 2 + 1] * MEMD + n];
    }
    a1 *= 0.125f; a2 *= 0.125f;

    float hv[NSLOT], p[NSLOT];
    #pragma unroll
    for (int jj = 0; jj < NSLOT; jj++) {
        hv[jj] = g_H[b * (NSLOT * MEMD) + jj * MEMD + n];
        p[jj] = hv[jj] * qv;
    }
    #pragma unroll
    for (int s = 16; s; s >>= 1)
        #pragma unroll
        for (int jj = 0; jj < NSLOT; jj++) p[jj] += __shfl_xor_sync(~0u, p[jj], s);
    if (l == 0) {
        #pragma unroll
        for (int jj = 0; jj < NSLOT; jj++) red[w][jj] = p[jj];
    }
    __syncthreads();
    if (n == 0) {
        float d[NSLOT], mx = -1e30f;
        #pragma unroll
        for (int jj = 0; jj < NSLOT; jj++) {
            d[jj] = red[0][jj] + red[1][jj] + red[2][jj] + red[3][jj];
            mx = fmaxf(mx, d[jj]);
        }
        float sm = 0.f;
        #pragma unroll
        for (int jj = 0; jj < NSLOT; jj++) { d[jj] = expf(d[jj] - mx); sm += d[jj]; }
        float inv = 1.f / sm;
        #pragma unroll
        for (int jj = 0; jj < NSLOT; jj++) p_s[jj] = d[jj] * inv;
    }
    __syncthreads();

    float u = 0.f;
    #pragma unroll
    for (int jj = 0; jj < NSLOT; jj++) u = fmaf(p_s[jj], hv[jj], u);
    u_s[n] = u;
    __syncthreads();

    // Hw matvec: 4 independent FMA chains, float4 loads
    float r0 = 0.f, r1 = 0.f, r2 = 0.f, r3 = 0.f;
    const float4* hw4 = (const float4*)(Hw + n * MEMD);
    const float4* u4  = (const float4*)u_s;
    #pragma unroll
    for (int i = 0; i < 32; i += 4) {
        float4 h0 = hw4[i],     x0 = u4[i];
        float4 h1 = hw4[i + 1], x1 = u4[i + 1];
        float4 h2 = hw4[i + 2], x2 = u4[i + 2];
        float4 h3 = hw4[i + 3], x3 = u4[i + 3];
        r0 = fmaf(x0.x, h0.x, fmaf(x0.y, h0.y, fmaf(x0.z, h0.z, fmaf(x0.w, h0.w, r0))));
        r1 = fmaf(x1.x, h1.x, fmaf(x1.y, h1.y, fmaf(x1.z, h1.z, fmaf(x1.w, h1.w, r1))));
        r2 = fmaf(x2.x, h2.x, fmaf(x2.y, h2.y, fmaf(x2.z, h2.z, fmaf(x2.w, h2.w, r2))));
        r3 = fmaf(x3.x, h3.x, fmaf(x3.y, h3.y, fmaf(x3.z, h3.z, fmaf(x3.w, h3.w, r3))));
    }
    float r = fmaxf(qv + Hb[n] + ((r0 + r1) + (r2 + r3)), 0.f);

    float y1 = r * a1, y2 = r * a2;
    #pragma unroll
    for (int s = 16; s; s >>= 1) {
        y1 += __shfl_xor_sync(~0u, y1, s);
        y2 += __shfl_xor_sync(~0u, y2, s);
    }
    if (l == 0) { yr[w][0] = y1; yr[w][1] = y2; }
    __syncthreads();
    if (n == 0) {
        float s1 = yr[0][0] + yr[1][0] + yr[2][0] + yr[3][0];
        float s2 = yr[0][1] + yr[1][1] + yr[2][1] + yr[3][1];
        float mx = fmaxf(s1, s2);
        float e1 = expf(s1 - mx), e2 = expf(s2 - mx);
        float inv = 1.f / (e1 + e2);
        out[b * 2 + 0] = e1 * inv;
        out[b * 2 + 1] = e2 * inv;
    }
}

extern "C" void kernel_launch(void* const* d_in, const int* in_sizes, int n_in,
                              void* d_out, int out_size) {
    const int*   input_ids = (const int*)  d_in[0];
    const int*   question  = (const int*)  d_in[1];
    const int*   ans       = (const int*)  d_in[2];
    const float* E         = (const float*)d_in[3];
    const float* Uw        = (const float*)d_in[4];
    const float* Ub        = (const float*)d_in[5];
    const float* Vw        = (const float*)d_in[6];
    const float* Vb        = (const float*)d_in[7];
    const float* Ww        = (const float*)d_in[8];
    const float* Wb        = (const float*)d_in[9];
    const float* sk        = (const float*)d_in[10];
    const float* Hw        = (const float*)d_in[11];
    const float* Hb        = (const float*)d_in[12];
    float* out = (float*)d_out;

    k_pro  <<<188, 256>>>(input_ids, E, Ww, Wb, sk, Vw, Vb);
    k_main <<<NCTA, 512>>>(Uw, Ub);
    k_epi  <<<64, 128>>>(question, ans, E, Hw, Hb, out);
}

// round 14
// speedup vs baseline: 1.0906x; 1.0016x over previous
#include <cuda_runtime.h>
#include <math.h>

#define NBATCH 64
#define NSTEP  128
#define MEMD   128
#define NSLOT  20
#define HSLOT  10
#define NCTA   128
#define OUTC   160
#define RSTR   12      // floats per mem_s row (48B, 16B aligned)

__device__ float g_S [NBATCH * NSTEP * MEMD];
__device__ float g_O [NBATCH * NSTEP * OUTC];
__device__ float g_VK[NSLOT * MEMD];
__device__ uint2 g_part[NSTEP][NSLOT][NBATCH];   // {value bits, tag = t+1}
__device__ float g_H [NBATCH * NSLOT * MEMD];

// ---------- helpers ----------
__device__ __forceinline__ void ffma2(unsigned long long &acc, unsigned long long a,
                                      unsigned long long b) {
    asm("fma.rn.f32x2 %0, %1, %2, %0;" : "+l"(acc) : "l"(a), "l"(b));
}
__device__ __forceinline__ unsigned long long add2(unsigned long long a,
                                                   unsigned long long b) {
    unsigned long long r;
    asm("add.rn.f32x2 %0, %1, %2;" : "=l"(r) : "l"(a), "l"(b));
    return r;
}
__device__ __forceinline__ unsigned long long pack2(float x) {
    unsigned long long r; asm("mov.b64 %0, {%1, %1};" : "=l"(r) : "f"(x)); return r;
}
__device__ __forceinline__ float2 up2(unsigned long long v) {
    float2 r; asm("mov.b64 {%0, %1}, %2;" : "=f"(r.x), "=f"(r.y) : "l"(v)); return r;
}
__device__ __forceinline__ unsigned smem_u32(const void* p) {
    return (unsigned)__cvta_generic_to_shared(p);
}
__device__ __forceinline__ void ld_row10(unsigned addr,
    unsigned long long &m0, unsigned long long &m1, unsigned long long &m2,
    unsigned long long &m3, unsigned long long &m4) {
    asm("{\n\t"
        ".reg .b32 t0,t1,t2,t3,t4,t5,t6,t7,t8,t9;\n\t"
        "ld.shared.v4.b32 {t0,t1,t2,t3}, [%5];\n\t"
        "ld.shared.v4.b32 {t4,t5,t6,t7}, [%5+16];\n\t"
        "ld.shared.v2.b32 {t8,t9}, [%5+32];\n\t"
        "mov.b64 %0, {t0,t1};\n\t"
        "mov.b64 %1, {t2,t3};\n\t"
        "mov.b64 %2, {t4,t5};\n\t"
        "mov.b64 %3, {t6,t7};\n\t"
        "mov.b64 %4, {t8,t9};\n\t"
        "}"
        : "=l"(m0), "=l"(m1), "=l"(m2), "=l"(m3), "=l"(m4) : "r"(addr));
}
__device__ __forceinline__ uint2 ldv2(const uint2* p) {
    uint2 v;
    asm volatile("ld.volatile.global.v2.u32 {%0,%1}, [%2];"
                 : "=r"(v.x), "=r"(v.y) : "l"(p) : "memory");
    return v;
}
__device__ __forceinline__ void stv2(uint2* p, uint2 v) {
    asm volatile("st.volatile.global.v2.u32 [%0], {%1,%2};"
                 :: "l"(p), "r"(v.x), "r"(v.y) : "memory");
}
__device__ __forceinline__ float sig(float x) { return 1.f / (1.f + __expf(-x)); }

// ---------- fused prologue (512 thr, R12 config): GEMM 0-127 + VK 128-147 + zero 148-167 ----------
// OUT[row][c] = E[tok[row]] . [Ww;sk][c] + [Wb;0][c]
__global__ void __launch_bounds__(512) k_pro(const int* __restrict__ ids,
                                             const float* __restrict__ E,
                                             const float* __restrict__ Ww,
                                             const float* __restrict__ Wb,
                                             const float* __restrict__ sk,
                                             const float* __restrict__ Vw,
                                             const float* __restrict__ Vb) {
    int bid = blockIdx.x, tid = threadIdx.x;
    if (bid >= 128) {
        if (bid < 148) {               // Vkey row (bid-128)
            if (tid < 128) {
                int j = bid - 128;
                float acc = Vb[tid];
                const float* skr = sk + j * MEMD;
                const float* vwr = Vw + tid * MEMD;
                #pragma unroll 8
                for (int m = 0; m < MEMD; m++) acc += skr[m] * vwr[m];
                g_VK[j * MEMD + tid] = acc;
            }
        } else {                        // zero g_part: 20 blocks x 512 thr x 8 uint4
            int base = (bid - 148) * 4096 + tid;
            #pragma unroll
            for (int i = 0; i < 8; i++)
                ((uint4*)g_part)[base + i * 512] = make_uint4(0u, 0u, 0u, 0u);
        }
        return;
    }
    __shared__ int   toks[64];
    __shared__ float Ss[64][33];
    __shared__ float Ks[OUTC][33];
    int row0 = bid * 64;
    int tx = tid & 15, ty = tid >> 4;            // tx: 10 cols, ty: 2 rows
    if (tid < 64) {
        int row = row0 + tid;
        toks[tid] = ids[(row >> 7) * 4096 + (row & 127)];
    }
    __syncthreads();
    float acc[2][10];
    #pragma unroll
    for (int i = 0; i < 2; i++)
        #pragma unroll
        for (int j = 0; j < 10; j++) acc[i][j] = 0.f;
    for (int kk = 0; kk < 128; kk += 32) {
        #pragma unroll
        for (int i = 0; i < 4; i++) {
            int idx = tid + i * 512, r = idx >> 5, k = idx & 31;
            float v = E[toks[r] * 128 + kk + k];
            Ss[r][k] = v;
            g_S[(row0 + r) * 128 + kk + k] = v;
        }
        #pragma unroll
        for (int i = 0; i < 10; i++) {
            int idx = tid + i * 512, c = idx >> 5, k = idx & 31;
            float v = 0.f;
            if (c < 128)      v = Ww[c * 128 + kk + k];
            else if (c < 148) v = sk[(c - 128) * 128 + kk + k];
            Ks[c][k] = v;
        }
        __syncthreads();
        #pragma unroll
        for (int k = 0; k < 32; k++) {
            float a[2], bv[10];
            #pragma unroll
            for (int i = 0; i < 2; i++)  a[i]  = Ss[ty * 2 + i][k];
            #pragma unroll
            for (int j = 0; j < 10; j++) bv[j] = Ks[tx * 10 + j][k];
            #pragma unroll
            for (int i = 0; i < 2; i++)
                #pragma unroll
                for (int j = 0; j < 10; j++) acc[i][j] = fmaf(a[i], bv[j], acc[i][j]);
        }
        __syncthreads();
    }
    #pragma unroll
    for (int i = 0; i < 2; i++)
        #pragma unroll
        for (int j = 0; j < 10; j++) {
            int r = row0 + ty * 2 + i, c = tx * 10 + j;
            float bk = (c < 128) ? Wb[c] : 0.f;
            g_O[r * OUTC + c] = acc[i][j] + bk;
        }
}

// ---------- persistent scan: R13 (publish-first epilogue), verbatim ----------
__global__ void __launch_bounds__(512, 1) k_main(const float* __restrict__ Uw,
                                                 const float* __restrict__ Ub) {
    __shared__ float mem_s[128 * RSTR];          // RAW (unnormalized) mem
    __shared__ float vk_s[HSLOT][128];
    __shared__ float s_b[2][128], ws_b[2][128];  // double-buffered staging
    __shared__ float sk_b[2][12];
    __shared__ float red_s[8][5];                // gate partials
    __shared__ float red2_s[16][4];              // sumsq partials per warp
    __shared__ float inv_s[HSLOT];
    __shared__ unsigned long long comb[5][4][128];  // [pair][quarter][n]

    const int tid = threadIdx.x;
    const int n = tid & 127, q = tid >> 7, wid = tid >> 5, lane = tid & 31;
    const int cta = blockIdx.x, b = cta >> 1, half = cta & 1;

    // pre-packed Uw column slice: 32 rows of this thread's k-quarter
    unsigned long long uwr2[32];
    {
        const float4* up = (const float4*)(Uw + n * 128 + q * 32);
        #pragma unroll
        for (int i = 0; i < 8; i++) {
            float4 v = up[i];
            uwr2[4*i]   = pack2(v.x); uwr2[4*i+1] = pack2(v.y);
            uwr2[4*i+2] = pack2(v.z); uwr2[4*i+3] = pack2(v.w);
        }
    }
    const float ubn = Ub[n];
    for (int idx = tid; idx < HSLOT * 128; idx += 512)
        vk_s[idx >> 7][idx & 127] = g_VK[(half * HSLOT + (idx >> 7)) * 128 + (idx & 127)];
    for (int idx = tid; idx < 128 * RSTR; idx += 512) mem_s[idx] = 0.f;

    float memv[4];
    #pragma unroll
    for (int i = 0; i < 4; i++) memv[i] = 0.f;

    const float* Sb = g_S + b * 128 * 128;
    const float* Ob = g_O + b * 128 * OUTC;
    if (q == 0) { s_b[0][n] = Sb[n]; ws_b[0][n] = Ob[n]; }
    else if (q == 1 && n < HSLOT) sk_b[0][n] = Ob[128 + half * HSLOT + n];
    if (tid < HSLOT) inv_s[tid] = 1.f;           // t=0: mem is exactly zero
    __syncthreads();

    const unsigned mem_u32 = smem_u32(mem_s) + q * 32 * (RSTR * 4);

    for (int t = 0; t < NSTEP; t++) {
        const int cur = t & 1, nxt = cur ^ 1;

        // ---- A. q0/q1: staging prefetch; q2/q3: raw gate dots ----
        float s_nxt = 0.f, ws_nxt = 0.f, skey_nxt = 0.f;
        if (q < 2) {
            int tn = (t + 1) & 127;
            if (q == 0) { s_nxt = Sb[tn * 128 + n]; ws_nxt = Ob[tn * OUTC + n]; }
            else if (n < HSLOT) skey_nxt = Ob[tn * OUTC + 128 + half * HSLOT + n];
        } else {
            float sv = s_b[cur][n];
            const float* row = mem_s + n * RSTR + (q - 2) * 5;
            float p0 = sv * row[0], p1 = sv * row[1], p2 = sv * row[2];
            float p3 = sv * row[3], p4 = sv * row[4];
            #pragma unroll
            for (int s = 16; s; s >>= 1) {
                p0 += __shfl_xor_sync(~0u, p0, s);
                p1 += __shfl_xor_sync(~0u, p1, s);
                p2 += __shfl_xor_sync(~0u, p2, s);
                p3 += __shfl_xor_sync(~0u, p3, s);
                p4 += __shfl_xor_sync(~0u, p4, s);
            }
            if (lane == 0) {
                float* rr = red_s[wid - 8];
                rr[0] = p0; rr[1] = p1; rr[2] = p2; rr[3] = p3; rr[4] = p4;
            }
        }

        // ---- B. matmul quarter: 32 rows x (3 LDS + 5 FFMA2) ----
        unsigned long long accv[5];
        #pragma unroll
        for (int p = 0; p < 5; p++) accv[p] = 0ull;
        #pragma unroll
        for (int k = 0; k < 32; k++) {
            unsigned long long m0, m1, m2, m3, m4;
            ld_row10(mem_u32 + k * (RSTR * 4), m0, m1, m2, m3, m4);
            ffma2(accv[0], uwr2[k], m0);
            ffma2(accv[1], uwr2[k], m1);
            ffma2(accv[2], uwr2[k], m2);
            ffma2(accv[3], uwr2[k], m3);
            ffma2(accv[4], uwr2[k], m4);
        }
        #pragma unroll
        for (int p = 0; p < 5; p++) comb[p][q][n] = accv[p];

        // ---- C. poll norms (warps 0-4, per-thread independent exit) ----
        if (t && wid < 5) {
            int j = tid >> 4, i = tid & 15;
            const uint2* pp = &g_part[t - 1][half * HSLOT + j][i];
            const unsigned want = (unsigned)t;
            uint2 v0 = ldv2(pp), v1 = ldv2(pp + 16), v2 = ldv2(pp + 32), v3 = ldv2(pp + 48);
            while ((v0.y ^ want) | (v1.y ^ want) | (v2.y ^ want) | (v3.y ^ want)) {
                v0 = ldv2(pp); v1 = ldv2(pp + 16); v2 = ldv2(pp + 32); v3 = ldv2(pp + 48);
            }
            float acc = __uint_as_float(v0.x) + __uint_as_float(v1.x)
                      + __uint_as_float(v2.x) + __uint_as_float(v3.x);
            acc += __shfl_xor_sync(~0u, acc, 8);
            acc += __shfl_xor_sync(~0u, acc, 4);
            acc += __shfl_xor_sync(~0u, acc, 2);
            acc += __shfl_xor_sync(~0u, acc, 1);
            if (i == 0) inv_s[j] = rsqrtf(acc);
        }
        __syncthreads();   // comb + red_s + inv_s all visible

        // ---- D. epilogue: publish path FIRST, mem/staging writes after ----
        const float wsv = ws_b[cur][n];
        float* row = mem_s + n * RSTR;
        const unsigned tagp = (unsigned)(t + 1);
        if (q == 0) {
            float sq[4];
            #pragma unroll
            for (int p = 0; p < 2; p++) {
                unsigned long long tot = add2(add2(comb[p][0][n], comb[p][1][n]),
                                              add2(comb[p][2][n], comb[p][3][n]));
                float2 a = up2(tot);
                const int j0 = 2 * p, j1 = 2 * p + 1;
                float r0 = red_s[0][j0] + red_s[1][j0] + red_s[2][j0] + red_s[3][j0];
                float r1 = red_s[0][j1] + red_s[1][j1] + red_s[2][j1] + red_s[3][j1];
                float i0 = inv_s[j0], i1 = inv_s[j1];
                float g0 = sig(fmaf(i0, r0, sk_b[cur][j0]));
                float g1 = sig(fmaf(i1, r1, sk_b[cur][j1]));
                float h0 = fmaxf(fmaf(i0, a.x, ubn + vk_s[j0][n] + wsv), 0.f);
                float h1 = fmaxf(fmaf(i1, a.y, ubn + vk_s[j1][n] + wsv), 0.f);
                memv[j0] = fmaf(memv[j0], i0, g0 * h0);
                memv[j1] = fmaf(memv[j1], i1, g1 * h1);
                sq[j0] = memv[j0] * memv[j0];
                sq[j1] = memv[j1] * memv[j1];
            }
            #pragma unroll
            for (int s = 16; s; s >>= 1)
                #pragma unroll
                for (int i = 0; i < 4; i++) sq[i] += __shfl_xor_sync(~0u, sq[i], s);
            if (lane == 0) {
                red2_s[wid][0] = sq[0]; red2_s[wid][1] = sq[1];
                red2_s[wid][2] = sq[2]; red2_s[wid][3] = sq[3];
            }
            asm volatile("bar.sync 1, 128;" ::: "memory");
            if (wid == 0 && lane < 4) {
                float v = red2_s[0][lane] + red2_s[1][lane] + red2_s[2][lane] + red2_s[3][lane];
                uint2 pkt; pkt.x = __float_as_uint(v); pkt.y = tagp;
                stv2(&g_part[t][half * HSLOT + lane][b], pkt);
            }
            // deferred writes (guarded by step-final __syncthreads)
            *(float4*)row = make_float4(memv[0], memv[1], memv[2], memv[3]);
            s_b[nxt][n] = s_nxt; ws_b[nxt][n] = ws_nxt;
        } else {
            const int p = q + 1;                 // pair owned: q1->2, q2->3, q3->4
            const int j0 = 2 * p, j1 = 2 * p + 1;
            unsigned long long tot = add2(add2(comb[p][0][n], comb[p][1][n]),
                                          add2(comb[p][2][n], comb[p][3][n]));
            float2 a = up2(tot);
            float r0 = (j0 < 5) ? red_s[0][j0] + red_s[1][j0] + red_s[2][j0] + red_s[3][j0]
                                : red_s[4][j0-5] + red_s[5][j0-5] + red_s[6][j0-5] + red_s[7][j0-5];
            float r1 = (j1 < 5) ? red_s[0][j1] + red_s[1][j1] + red_s[2][j1] + red_s[3][j1]
                                : red_s[4][j1-5] + red_s[5][j1-5] + red_s[6][j1-5] + red_s[7][j1-5];
            float i0 = inv_s[j0], i1 = inv_s[j1];
            float g0 = sig(fmaf(i0, r0, sk_b[cur][j0]));
            float g1 = sig(fmaf(i1, r1, sk_b[cur][j1]));
            float h0 = fmaxf(fmaf(i0, a.x, ubn + vk_s[j0][n] + wsv), 0.f);
            float h1 = fmaxf(fmaf(i1, a.y, ubn + vk_s[j1][n] + wsv), 0.f);
            memv[0] = fmaf(memv[0], i0, g0 * h0);
            memv[1] = fmaf(memv[1], i1, g1 * h1);
            float sq0 = memv[0] * memv[0], sq1 = memv[1] * memv[1];
            #pragma unroll
            for (int s = 16; s; s >>= 1) {
                sq0 += __shfl_xor_sync(~0u, sq0, s);
                sq1 += __shfl_xor_sync(~0u, sq1, s);
            }
            if (lane == 0) { red2_s[wid][0] = sq0; red2_s[wid][1] = sq1; }
            if (q == 1)      asm volatile("bar.sync 2, 128;" ::: "memory");
            else if (q == 2) asm volatile("bar.sync 3, 128;" ::: "memory");
            else             asm volatile("bar.sync 4, 128;" ::: "memory");
            if ((wid & 3) == 0 && lane < 2) {
                int w0 = q * 4;
                float v = red2_s[w0][lane] + red2_s[w0+1][lane]
                        + red2_s[w0+2][lane] + red2_s[w0+3][lane];
                uint2 pkt; pkt.x = __float_as_uint(v); pkt.y = tagp;
                stv2(&g_part[t][half * HSLOT + j0 + lane][b], pkt);
            }
            // deferred writes
            *(float2*)(row + j0) = make_float2(memv[0], memv[1]);
            if (q == 1 && n < HSLOT) sk_b[nxt][n] = skey_nxt;
        }
        __syncthreads();   // mem(t+1) + staging visible for next step
    }

    // ---- final normalization ----
    if (wid < 5) {
        int j = tid >> 4, i = tid & 15;
        const uint2* pp = &g_part[NSTEP - 1][half * HSLOT + j][i];
        const unsigned want = (unsigned)NSTEP;
        uint2 v0 = ldv2(pp), v1 = ldv2(pp + 16), v2 = ldv2(pp + 32), v3 = ldv2(pp + 48);
        while ((v0.y ^ want) | (v1.y ^ want) | (v2.y ^ want) | (v3.y ^ want)) {
            v0 = ldv2(pp); v1 = ldv2(pp + 16); v2 = ldv2(pp + 32); v3 = ldv2(pp + 48);
        }
        float acc = __uint_as_float(v0.x) + __uint_as_float(v1.x)
                  + __uint_as_float(v2.x) + __uint_as_float(v3.x);
        acc += __shfl_xor_sync(~0u, acc, 8);
        acc += __shfl_xor_sync(~0u, acc, 4);
        acc += __shfl_xor_sync(~0u, acc, 2);
        acc += __shfl_xor_sync(~0u, acc, 1);
        if (i == 0) inv_s[j] = rsqrtf(acc);
    }
    __syncthreads();

    {
        float* gh = g_H + b * (NSLOT * MEMD) + half * HSLOT * MEMD;
        if (q == 0) {
            #pragma unroll
            for (int j = 0; j < 4; j++) gh[j * MEMD + n] = memv[j] * inv_s[j];
        } else {
            const int j0 = 2 * (q + 1);
            gh[j0 * MEMD + n]       = memv[0] * inv_s[j0];
            gh[(j0 + 1) * MEMD + n] = memv[1] * inv_s[j0 + 1];
        }
    }
}

// ---------- epilogue ----------
__global__ void k_epi(const int* __restrict__ q, const int* __restrict__ ans,
                      const float* __restrict__ E, const float* __restrict__ Hw,
                      const float* __restrict__ Hb, float* __restrict__ out) {
    __shared__ float red[4][NSLOT];
    __shared__ float p_s[NSLOT];
    __shared__ __align__(16) float u_s[MEMD];
    __shared__ float yr[4][2];
    int b = blockIdx.x, n = threadIdx.x, w = n >> 5, l = n & 31;

    float qv = 0.f;
    #pragma unroll
    for (int i = 0; i < 16; i++) qv += E[q[b * 16 + i] * MEMD + n];
    qv *= (1.f / 16.f);
    float a1 = 0.f, a2 = 0.f;
    #pragma unroll
    for (int i = 0; i < 8; i++) {
        a1 += E[ans[(b * 8 + i) * 2 + 0] * MEMD + n];
        a2 += E[ans[(b * 8 + i) * 2 + 1] * MEMD + n];
    }
    a1 *= 0.125f; a2 *= 0.125f;

    float hv[NSLOT], p[NSLOT];
    #pragma unroll
    for (int jj = 0; jj < NSLOT; jj++) {
        hv[jj] = g_H[b * (NSLOT * MEMD) + jj * MEMD + n];
        p[jj] = hv[jj] * qv;
    }
    #pragma unroll
    for (int s = 16; s; s >>= 1)
        #pragma unroll
        for (int jj = 0; jj < NSLOT; jj++) p[jj] += __shfl_xor_sync(~0u, p[jj], s);
    if (l == 0) {
        #pragma unroll
        for (int jj = 0; jj < NSLOT; jj++) red[w][jj] = p[jj];
    }
    __syncthreads();
    if (n == 0) {
        float d[NSLOT], mx = -1e30f;
        #pragma unroll
        for (int jj = 0; jj < NSLOT; jj++) {
            d[jj] = red[0][jj] + red[1][jj] + red[2][jj] + red[3][jj];
            mx = fmaxf(mx, d[jj]);
        }
        float sm = 0.f;
        #pragma unroll
        for (int jj = 0; jj < NSLOT; jj++) { d[jj] = expf(d[jj] - mx); sm += d[jj]; }
        float inv = 1.f / sm;
        #pragma unroll
        for (int jj = 0; jj < NSLOT; jj++) p_s[jj] = d[jj] * inv;
    }
    __syncthreads();

    float u = 0.f;
    #pragma unroll
    for (int jj = 0; jj < NSLOT; jj++) u = fmaf(p_s[jj], hv[jj], u);
    u_s[n] = u;
    __syncthreads();

    // Hw matvec: 4 independent FMA chains, float4 loads
    float r0 = 0.f, r1 = 0.f, r2 = 0.f, r3 = 0.f;
    const float4* hw4 = (const float4*)(Hw + n * MEMD);
    const float4* u4  = (const float4*)u_s;
    #pragma unroll
    for (int i = 0; i < 32; i += 4) {
        float4 h0 = hw4[i],     x0 = u4[i];
        float4 h1 = hw4[i + 1], x1 = u4[i + 1];
        float4 h2 = hw4[i + 2], x2 = u4[i + 2];
        float4 h3 = hw4[i + 3], x3 = u4[i + 3];
        r0 = fmaf(x0.x, h0.x, fmaf(x0.y, h0.y, fmaf(x0.z, h0.z, fmaf(x0.w, h0.w, r0))));
        r1 = fmaf(x1.x, h1.x, fmaf(x1.y, h1.y, fmaf(x1.z, h1.z, fmaf(x1.w, h1.w, r1))));
        r2 = fmaf(x2.x, h2.x, fmaf(x2.y, h2.y, fmaf(x2.z, h2.z, fmaf(x2.w, h2.w, r2))));
        r3 = fmaf(x3.x, h3.x, fmaf(x3.y, h3.y, fmaf(x3.z, h3.z, fmaf(x3.w, h3.w, r3))));
    }
    float r = fmaxf(qv + Hb[n] + ((r0 + r1) + (r2 + r3)), 0.f);

    float y1 = r * a1, y2 = r * a2;
    #pragma unroll
    for (int s = 16; s; s >>= 1) {
        y1 += __shfl_xor_sync(~0u, y1, s);
        y2 += __shfl_xor_sync(~0u, y2, s);
    }
    if (l == 0) { yr[w][0] = y1; yr[w][1] = y2; }
    __syncthreads();
    if (n == 0) {
        float s1 = yr[0][0] + yr[1][0] + yr[2][0] + yr[3][0];
        float s2 = yr[0][1] + yr[1][1] + yr[2][1] + yr[3][1];
        float mx = fmaxf(s1, s2);
        float e1 = expf(s1 - mx), e2 = expf(s2 - mx);
        float inv = 1.f / (e1 + e2);
        out[b * 2 + 0] = e1 * inv;
        out[b * 2 + 1] = e2 * inv;
    }
}

extern "C" void kernel_launch(void* const* d_in, const int* in_sizes, int n_in,
                              void* d_out, int out_size) {
    const int*   input_ids = (const int*)  d_in[0];
    const int*   question  = (const int*)  d_in[1];
    const int*   ans       = (const int*)  d_in[2];
    const float* E         = (const float*)d_in[3];
    const float* Uw        = (const float*)d_in[4];
    const float* Ub        = (const float*)d_in[5];
    const float* Vw        = (const float*)d_in[6];
    const float* Vb        = (const float*)d_in[7];
    const float* Ww        = (const float*)d_in[8];
    const float* Wb        = (const float*)d_in[9];
    const float* sk        = (const float*)d_in[10];
    const float* Hw        = (const float*)d_in[11];
    const float* Hb        = (const float*)d_in[12];
    float* out = (float*)d_out;

    k_pro  <<<168, 512>>>(input_ids, E, Ww, Wb, sk, Vw, Vb);
    k_main <<<NCTA, 512>>>(Uw, Ub);
    k_epi  <<<64, 128>>>(question, ans, E, Hw, Hb, out);
}